// round 2
// baseline (speedup 1.0000x reference)
#include <cuda_runtime.h>

#define B_    32
#define T_    24
#define N_    512
#define BT    768
#define DIN   64
#define HID   128
#define EMB   16
#define DOUT  2
#define ROWS  64
#define NEG   0.01f

#define XS_LD 68     // padded leading dim for 64-wide x tile (bank-conflict-free row broadcast)
#define HS_LD 132    // padded leading dim for 128-wide tiles

// Inter-kernel scratch: out_spa [BT, N, HID]  (~201 MB, static device alloc per rules)
__device__ float g_spa[(size_t)BT * N_ * HID];

__device__ __forceinline__ float lrelu(float x) { return x >= 0.f ? x : NEG * x; }

// ---------------------------------------------------------------------------
// Kernel A: spatial stage. One block per node n.
//   h1 = eb[:, :, n, :] @ W1 + b1
//   out_spa[:, :, n, :] = leaky(h1 @ W_spa[n] + b_spa[n])
// ---------------------------------------------------------------------------
__global__ void __launch_bounds__(256, 1)
k_spatial(const float* __restrict__ eb,
          const float* __restrict__ node_eb,
          const float* __restrict__ W1,
          const float* __restrict__ b1,
          const float* __restrict__ pool_w,   // [EMB, HID, HID]
          const float* __restrict__ pool_b)   // [EMB, HID]
{
    extern __shared__ float sm[];
    float* W1s = sm;                      // DIN*HID      = 8192
    float* Wsp = W1s + DIN * HID;         // HID*HID      = 16384
    float* xs  = Wsp + HID * HID;         // ROWS*XS_LD   = 4352
    float* h1s = xs  + ROWS * XS_LD;      // ROWS*HS_LD   = 8448
    float* b1s = h1s + ROWS * HS_LD;      // HID
    float* bsp = b1s + HID;               // HID

    const int n = blockIdx.x;
    const int t = threadIdx.x;

    // node embedding (uniform across block; broadcast LDG)
    float ne[EMB];
#pragma unroll
    for (int d = 0; d < EMB; d++) ne[d] = node_eb[n * EMB + d];

    // W1 + biases into smem
    for (int e = t; e < DIN * HID; e += 256) W1s[e] = W1[e];
    if (t < HID) {
        b1s[t] = b1[t];
        float s = 0.f;
#pragma unroll
        for (int d = 0; d < EMB; d++) s += ne[d] * pool_b[d * HID + t];
        bsp[t] = s;
    }
    // Generate W_spa[n] = sum_d ne[d] * pool_w[d]  (coalesced, L2-resident pool)
    for (int e = t; e < HID * HID; e += 256) {
        float s = 0.f;
#pragma unroll
        for (int d = 0; d < EMB; d++) s += ne[d] * pool_w[d * HID * HID + e];
        Wsp[e] = s;
    }

    const int rg = t >> 4;   // row group: rows rg*4 .. rg*4+3
    const int cg = t & 15;   // col group: cols cg*8 .. cg*8+7
    __syncthreads();

    for (int c0 = 0; c0 < BT; c0 += ROWS) {
        // ---- load x tile [ROWS, DIN] (rows strided by N*DIN in global) ----
        for (int f = t; f < ROWS * (DIN / 4); f += 256) {
            int r = f >> 4, q = f & 15;
            float4 v = *(const float4*)(eb + ((size_t)(c0 + r) * N_ + n) * DIN + q * 4);
            *(float4*)(xs + r * XS_LD + q * 4) = v;
        }
        __syncthreads();   // xs ready; also: all threads done reading h1s from prev iter

        // ---- stage 1: h1 = x @ W1 + b1 ----
        float acc[4][8];
#pragma unroll
        for (int i = 0; i < 4; i++)
#pragma unroll
            for (int j = 0; j < 8; j++) acc[i][j] = b1s[cg * 8 + j];

#pragma unroll 8
        for (int k = 0; k < DIN; k++) {
            float a[4];
#pragma unroll
            for (int i = 0; i < 4; i++) a[i] = xs[(rg * 4 + i) * XS_LD + k];
            float4 w0 = *(float4*)(W1s + k * HID + cg * 8);
            float4 w1 = *(float4*)(W1s + k * HID + cg * 8 + 4);
            float w[8] = {w0.x, w0.y, w0.z, w0.w, w1.x, w1.y, w1.z, w1.w};
#pragma unroll
            for (int i = 0; i < 4; i++)
#pragma unroll
                for (int j = 0; j < 8; j++) acc[i][j] += a[i] * w[j];
        }
#pragma unroll
        for (int i = 0; i < 4; i++) {
            float4 v0 = {acc[i][0], acc[i][1], acc[i][2], acc[i][3]};
            float4 v1 = {acc[i][4], acc[i][5], acc[i][6], acc[i][7]};
            *(float4*)(h1s + (rg * 4 + i) * HS_LD + cg * 8)     = v0;
            *(float4*)(h1s + (rg * 4 + i) * HS_LD + cg * 8 + 4) = v1;
        }
        __syncthreads();   // h1s ready

        // ---- stage 2: out = leaky(h1 @ Wsp + bsp) ----
        float acc2[4][8];
#pragma unroll
        for (int i = 0; i < 4; i++)
#pragma unroll
            for (int j = 0; j < 8; j++) acc2[i][j] = bsp[cg * 8 + j];

#pragma unroll 8
        for (int k = 0; k < HID; k++) {
            float a[4];
#pragma unroll
            for (int i = 0; i < 4; i++) a[i] = h1s[(rg * 4 + i) * HS_LD + k];
            float4 w0 = *(float4*)(Wsp + k * HID + cg * 8);
            float4 w1 = *(float4*)(Wsp + k * HID + cg * 8 + 4);
            float w[8] = {w0.x, w0.y, w0.z, w0.w, w1.x, w1.y, w1.z, w1.w};
#pragma unroll
            for (int i = 0; i < 4; i++)
#pragma unroll
                for (int j = 0; j < 8; j++) acc2[i][j] += a[i] * w[j];
        }
#pragma unroll
        for (int i = 0; i < 4; i++) {
            float4 v0 = {lrelu(acc2[i][0]), lrelu(acc2[i][1]), lrelu(acc2[i][2]), lrelu(acc2[i][3])};
            float4 v1 = {lrelu(acc2[i][4]), lrelu(acc2[i][5]), lrelu(acc2[i][6]), lrelu(acc2[i][7])};
            float* dst = g_spa + ((size_t)(c0 + rg * 4 + i) * N_ + n) * HID + cg * 8;
            *(float4*)(dst)     = v0;
            *(float4*)(dst + 4) = v1;
        }
        // no sync needed here: next-iter sync after xs load also fences h1s reads
    }
}

// ---------------------------------------------------------------------------
// Kernel B: temporal stage. One block per (b,t).
//   h = leaky(out_spa[bt] @ W_tem[bt] + b_tem[bt])
//   out[bt] = h @ W3 + b3
// ---------------------------------------------------------------------------
__global__ void __launch_bounds__(256, 1)
k_temporal(const float* __restrict__ time_eb,
           const float* __restrict__ pool_w,   // [EMB, HID, HID]
           const float* __restrict__ pool_b,   // [EMB, HID]
           const float* __restrict__ W3,       // [HID, DOUT]
           const float* __restrict__ b3,       // [DOUT]
           float* __restrict__ out)
{
    extern __shared__ float sm[];
    float* Wtm = sm;                      // HID*HID    = 16384
    float* ss  = Wtm + HID * HID;         // ROWS*HS_LD = 8448
    float* hs  = ss  + ROWS * HS_LD;      // ROWS*HS_LD = 8448
    float* btm = hs  + ROWS * HS_LD;      // HID
    float* W3s = btm + HID;               // HID*DOUT
    float* b3s = W3s + HID * DOUT;        // DOUT

    const int bt = blockIdx.x;
    const int t  = threadIdx.x;

    float te[EMB];
#pragma unroll
    for (int d = 0; d < EMB; d++) te[d] = time_eb[bt * EMB + d];

    if (t < HID) {
        float s = 0.f;
#pragma unroll
        for (int d = 0; d < EMB; d++) s += te[d] * pool_b[d * HID + t];
        btm[t] = s;
    }
    if (t < HID * DOUT) W3s[t] = W3[t];
    if (t < DOUT)       b3s[t] = b3[t];

    for (int e = t; e < HID * HID; e += 256) {
        float s = 0.f;
#pragma unroll
        for (int d = 0; d < EMB; d++) s += te[d] * pool_w[d * HID * HID + e];
        Wtm[e] = s;
    }

    const int rg = t >> 4;
    const int cg = t & 15;
    __syncthreads();

    for (int n0 = 0; n0 < N_; n0 += ROWS) {
        // ---- load out_spa tile [ROWS, HID] (fully contiguous) ----
        for (int f = t; f < ROWS * (HID / 4); f += 256) {
            int r = f >> 5, q = f & 31;
            float4 v = *(const float4*)(g_spa + ((size_t)bt * N_ + n0 + r) * HID + q * 4);
            *(float4*)(ss + r * HS_LD + q * 4) = v;
        }
        __syncthreads();   // ss ready; fences prev-iter hs readers before hs rewrite

        // ---- h = leaky(s @ Wtm + btm) ----
        float acc[4][8];
#pragma unroll
        for (int i = 0; i < 4; i++)
#pragma unroll
            for (int j = 0; j < 8; j++) acc[i][j] = btm[cg * 8 + j];

#pragma unroll 8
        for (int k = 0; k < HID; k++) {
            float a[4];
#pragma unroll
            for (int i = 0; i < 4; i++) a[i] = ss[(rg * 4 + i) * HS_LD + k];
            float4 w0 = *(float4*)(Wtm + k * HID + cg * 8);
            float4 w1 = *(float4*)(Wtm + k * HID + cg * 8 + 4);
            float w[8] = {w0.x, w0.y, w0.z, w0.w, w1.x, w1.y, w1.z, w1.w};
#pragma unroll
            for (int i = 0; i < 4; i++)
#pragma unroll
                for (int j = 0; j < 8; j++) acc[i][j] += a[i] * w[j];
        }
#pragma unroll
        for (int i = 0; i < 4; i++) {
            float4 v0 = {lrelu(acc[i][0]), lrelu(acc[i][1]), lrelu(acc[i][2]), lrelu(acc[i][3])};
            float4 v1 = {lrelu(acc[i][4]), lrelu(acc[i][5]), lrelu(acc[i][6]), lrelu(acc[i][7])};
            *(float4*)(hs + (rg * 4 + i) * HS_LD + cg * 8)     = v0;
            *(float4*)(hs + (rg * 4 + i) * HS_LD + cg * 8 + 4) = v1;
        }
        __syncthreads();   // hs ready

        // ---- logits = h @ W3 + b3  (64 rows x 2 outputs) ----
        if (t < ROWS * DOUT) {
            int r = t >> 1, c = t & 1;
            float s = b3s[c];
#pragma unroll 8
            for (int k = 0; k < HID; k++) s += hs[r * HS_LD + k] * W3s[k * DOUT + c];
            out[((size_t)bt * N_ + n0 + r) * DOUT + c] = s;
        }
        // next-iter sync after ss load fences hs reads before rewrite
    }
}

// ---------------------------------------------------------------------------
extern "C" void kernel_launch(void* const* d_in, const int* in_sizes, int n_in,
                              void* d_out, int out_size)
{
    const float* eb   = (const float*)d_in[0];   // [B,T,N,DIN]
    const float* teb  = (const float*)d_in[1];   // [B,T,EMB]
    const float* neb  = (const float*)d_in[2];   // [N,EMB]
    const float* W1   = (const float*)d_in[3];   // [DIN,HID]
    const float* b1   = (const float*)d_in[4];   // [HID]
    const float* W3   = (const float*)d_in[5];   // [HID,DOUT]
    const float* b3   = (const float*)d_in[6];   // [DOUT]
    const float* pws  = (const float*)d_in[7];   // [EMB,HID,HID]
    const float* pbs  = (const float*)d_in[8];   // [EMB,HID]
    const float* pwt  = (const float*)d_in[9];   // [EMB,HID,HID]
    const float* pbt  = (const float*)d_in[10];  // [EMB,HID]
    float* out = (float*)d_out;

    const size_t sm1 = (size_t)(DIN * HID + HID * HID + ROWS * XS_LD + ROWS * HS_LD + 2 * HID) * sizeof(float);
    const size_t sm2 = (size_t)(HID * HID + 2 * ROWS * HS_LD + HID + HID * DOUT + DOUT) * sizeof(float);

    cudaFuncSetAttribute((const void*)k_spatial,  cudaFuncAttributeMaxDynamicSharedMemorySize, (int)sm1);
    cudaFuncSetAttribute((const void*)k_temporal, cudaFuncAttributeMaxDynamicSharedMemorySize, (int)sm2);

    k_spatial<<<N_, 256, sm1>>>(eb, neb, W1, b1, pws, pbs);
    k_temporal<<<BT, 256, sm2>>>(teb, pwt, pbt, W3, b3, out);
}

// round 3
// speedup vs baseline: 1.4544x; 1.4544x over previous
#include <cuda_runtime.h>

#define B_    32
#define T_    24
#define N_    512
#define BT    768
#define DIN   64
#define HID   128
#define EMB   16
#define DOUT  2
#define ROWS  64
#define NEG   0.01f

#define XS_LD 68
#define SS_LD 132

// Inter-kernel scratch: out_spa [BT, N, HID]
__device__ float g_spa[(size_t)BT * N_ * HID];

__device__ __forceinline__ float lrelu(float x) { return x >= 0.f ? x : NEG * x; }

// ---------------------------------------------------------------------------
// Kernel A (spatial), fused form:
//   W_eff[n] = W1 @ W_spa[n]            (64x128, K=128)
//   b_eff[n] = b1 @ W_spa[n] + b_spa[n]
//   out_spa[:, :, n, :] = leaky(eb[:,:,n,:] @ W_eff[n] + b_eff[n])   (K=64)
// smem: [Wsp 16384 | W1s 8192 (xs overlay) | beff 128]  = ~98.8 KB -> 2 CTA/SM
// grid: (N_, 2) — y splits the 12 bt-tiles into 6+6.
// ---------------------------------------------------------------------------
__global__ void __launch_bounds__(256, 2)
k_spatial(const float* __restrict__ eb,
          const float* __restrict__ node_eb,
          const float* __restrict__ W1,
          const float* __restrict__ b1,
          const float* __restrict__ pool_w,   // [EMB, HID, HID]
          const float* __restrict__ pool_b)   // [EMB, HID]
{
    extern __shared__ float sm[];
    float* Wsp  = sm;                 // 128x128; later re-used as W_eff (64x128)
    float* W1s  = sm + HID * HID;     // 64x128;  later re-used as xs (64 x XS_LD)
    float* beff = W1s + DIN * HID;    // 128

    const int n = blockIdx.x;
    const int t = threadIdx.x;
    const int rg = t >> 4;   // 16 row groups x 4 rows
    const int cg = t & 15;   // 16 col groups x 8 cols

    float ne[EMB];
#pragma unroll
    for (int d = 0; d < EMB; d++) ne[d] = node_eb[n * EMB + d];

    // stage W1 and generate W_spa[n]
    for (int e = t; e < DIN * HID; e += 256) W1s[e] = W1[e];
    for (int e = t; e < HID * HID; e += 256) {
        float s = 0.f;
#pragma unroll
        for (int d = 0; d < EMB; d++) s += ne[d] * pool_w[d * HID * HID + e];
        Wsp[e] = s;
    }
    __syncthreads();

    // W_eff = W1 @ Wsp  (rows i<64 = rg*4+i, cols o = cg*8..)
    float acc[4][8];
#pragma unroll
    for (int i = 0; i < 4; i++)
#pragma unroll
        for (int j = 0; j < 8; j++) acc[i][j] = 0.f;

#pragma unroll 8
    for (int k = 0; k < HID; k++) {
        float a[4];
#pragma unroll
        for (int i = 0; i < 4; i++) a[i] = W1s[(rg * 4 + i) * HID + k];
        float4 w0 = *(float4*)(Wsp + k * HID + cg * 8);
        float4 w1 = *(float4*)(Wsp + k * HID + cg * 8 + 4);
        float w[8] = {w0.x, w0.y, w0.z, w0.w, w1.x, w1.y, w1.z, w1.w};
#pragma unroll
        for (int i = 0; i < 4; i++)
#pragma unroll
            for (int j = 0; j < 8; j++) acc[i][j] += a[i] * w[j];
    }

    // b_eff = b1 @ Wsp + node_eb @ pool_b   (needs Wsp: do before overwrite)
    if (t < HID) {
        float s = 0.f;
#pragma unroll 8
        for (int k = 0; k < HID; k++) s += b1[k] * Wsp[k * HID + t];
#pragma unroll
        for (int d = 0; d < EMB; d++) s += ne[d] * pool_b[d * HID + t];
        beff[t] = s;
    }
    __syncthreads();   // all Wsp reads complete

    // store W_eff over the Wsp region (64x128, LD=128)
#pragma unroll
    for (int i = 0; i < 4; i++) {
        *(float4*)(Wsp + (rg * 4 + i) * HID + cg * 8)     = make_float4(acc[i][0], acc[i][1], acc[i][2], acc[i][3]);
        *(float4*)(Wsp + (rg * 4 + i) * HID + cg * 8 + 4) = make_float4(acc[i][4], acc[i][5], acc[i][6], acc[i][7]);
    }
    float* Weff = Wsp;
    float* xs   = W1s;   // 64 x XS_LD fits in the 8192-float W1 region
    __syncthreads();

    const int c_base = blockIdx.y * (BT / 2);
    for (int cc = 0; cc < BT / 2; cc += ROWS) {
        const int c0 = c_base + cc;
        // load x tile [64 x 64]
        for (int f = t; f < ROWS * (DIN / 4); f += 256) {
            int r = f >> 4, q = f & 15;
            float4 v = *(const float4*)(eb + ((size_t)(c0 + r) * N_ + n) * DIN + q * 4);
            *(float4*)(xs + r * XS_LD + q * 4) = v;
        }
        __syncthreads();

        float a2[4][8];
#pragma unroll
        for (int i = 0; i < 4; i++)
#pragma unroll
            for (int j = 0; j < 8; j++) a2[i][j] = beff[cg * 8 + j];

#pragma unroll 8
        for (int k = 0; k < DIN; k++) {
            float a[4];
#pragma unroll
            for (int i = 0; i < 4; i++) a[i] = xs[(rg * 4 + i) * XS_LD + k];
            float4 w0 = *(float4*)(Weff + k * HID + cg * 8);
            float4 w1 = *(float4*)(Weff + k * HID + cg * 8 + 4);
            float w[8] = {w0.x, w0.y, w0.z, w0.w, w1.x, w1.y, w1.z, w1.w};
#pragma unroll
            for (int i = 0; i < 4; i++)
#pragma unroll
                for (int j = 0; j < 8; j++) a2[i][j] += a[i] * w[j];
        }
#pragma unroll
        for (int i = 0; i < 4; i++) {
            float* dst = g_spa + ((size_t)(c0 + rg * 4 + i) * N_ + n) * HID + cg * 8;
            *(float4*)(dst)     = make_float4(lrelu(a2[i][0]), lrelu(a2[i][1]), lrelu(a2[i][2]), lrelu(a2[i][3]));
            *(float4*)(dst + 4) = make_float4(lrelu(a2[i][4]), lrelu(a2[i][5]), lrelu(a2[i][6]), lrelu(a2[i][7]));
        }
        __syncthreads();   // xs reads complete before next load
    }
}

// ---------------------------------------------------------------------------
// Kernel B (temporal): one block per (bt, n-half).
//   h = leaky(out_spa[bt] @ W_tem[bt] + b_tem[bt]);  out = h @ W3 + b3
// Epilogue done in registers + shfl reduction (no hs buffer).
// smem: [Wtm 16384 | ss 64*132 | btm 128] = ~98.2 KB -> 2 CTA/SM
// ---------------------------------------------------------------------------
__global__ void __launch_bounds__(256, 2)
k_temporal(const float* __restrict__ time_eb,
           const float* __restrict__ pool_w,   // [EMB, HID, HID]
           const float* __restrict__ pool_b,   // [EMB, HID]
           const float* __restrict__ W3,       // [HID, DOUT]
           const float* __restrict__ b3,       // [DOUT]
           float* __restrict__ out)
{
    extern __shared__ float sm[];
    float* Wtm = sm;                  // 128x128
    float* ss  = Wtm + HID * HID;     // 64 x SS_LD
    float* btm = ss + ROWS * SS_LD;   // 128

    const int bt = blockIdx.x;
    const int t  = threadIdx.x;
    const int rg = t >> 4;
    const int cg = t & 15;

    float te[EMB];
#pragma unroll
    for (int d = 0; d < EMB; d++) te[d] = time_eb[bt * EMB + d];

    if (t < HID) {
        float s = 0.f;
#pragma unroll
        for (int d = 0; d < EMB; d++) s += te[d] * pool_b[d * HID + t];
        btm[t] = s;
    }
    for (int e = t; e < HID * HID; e += 256) {
        float s = 0.f;
#pragma unroll
        for (int d = 0; d < EMB; d++) s += te[d] * pool_w[d * HID * HID + e];
        Wtm[e] = s;
    }

    // per-thread W3 slice + b3 (L2/L1 broadcast reads)
    float w3r[8][2];
#pragma unroll
    for (int j = 0; j < 8; j++) {
        w3r[j][0] = W3[(cg * 8 + j) * DOUT + 0];
        w3r[j][1] = W3[(cg * 8 + j) * DOUT + 1];
    }
    const float b30 = b3[0], b31 = b3[1];
    __syncthreads();

    const int n_base = blockIdx.y * (N_ / 2);
    for (int nn = 0; nn < N_ / 2; nn += ROWS) {
        const int n0 = n_base + nn;
        // load out_spa tile [64 x 128] (contiguous)
        for (int f = t; f < ROWS * (HID / 4); f += 256) {
            int r = f >> 5, q = f & 31;
            float4 v = *(const float4*)(g_spa + ((size_t)bt * N_ + n0 + r) * HID + q * 4);
            *(float4*)(ss + r * SS_LD + q * 4) = v;
        }
        __syncthreads();

        float acc[4][8];
#pragma unroll
        for (int i = 0; i < 4; i++)
#pragma unroll
            for (int j = 0; j < 8; j++) acc[i][j] = btm[cg * 8 + j];

#pragma unroll 8
        for (int k = 0; k < HID; k++) {
            float a[4];
#pragma unroll
            for (int i = 0; i < 4; i++) a[i] = ss[(rg * 4 + i) * SS_LD + k];
            float4 w0 = *(float4*)(Wtm + k * HID + cg * 8);
            float4 w1 = *(float4*)(Wtm + k * HID + cg * 8 + 4);
            float w[8] = {w0.x, w0.y, w0.z, w0.w, w1.x, w1.y, w1.z, w1.w};
#pragma unroll
            for (int i = 0; i < 4; i++)
#pragma unroll
                for (int j = 0; j < 8; j++) acc[i][j] += a[i] * w[j];
        }

        // epilogue: h = leaky(acc); p = h @ W3 (partial over this thread's 8 cols)
        float p[4][2];
#pragma unroll
        for (int i = 0; i < 4; i++) {
            p[i][0] = 0.f; p[i][1] = 0.f;
#pragma unroll
            for (int j = 0; j < 8; j++) {
                float h = lrelu(acc[i][j]);
                p[i][0] += h * w3r[j][0];
                p[i][1] += h * w3r[j][1];
            }
        }
        // reduce across the 16 cg lanes (xor stays within 16-lane halves)
#pragma unroll
        for (int off = 8; off >= 1; off >>= 1) {
#pragma unroll
            for (int i = 0; i < 4; i++) {
                p[i][0] += __shfl_xor_sync(0xffffffffu, p[i][0], off);
                p[i][1] += __shfl_xor_sync(0xffffffffu, p[i][1], off);
            }
        }
        if (cg == 0) {
#pragma unroll
            for (int i = 0; i < 4; i++) {
                size_t o = ((size_t)bt * N_ + n0 + rg * 4 + i) * DOUT;
                out[o + 0] = p[i][0] + b30;
                out[o + 1] = p[i][1] + b31;
            }
        }
        __syncthreads();   // ss reads complete before next load
    }
}

// ---------------------------------------------------------------------------
extern "C" void kernel_launch(void* const* d_in, const int* in_sizes, int n_in,
                              void* d_out, int out_size)
{
    const float* eb   = (const float*)d_in[0];
    const float* teb  = (const float*)d_in[1];
    const float* neb  = (const float*)d_in[2];
    const float* W1   = (const float*)d_in[3];
    const float* b1   = (const float*)d_in[4];
    const float* W3   = (const float*)d_in[5];
    const float* b3   = (const float*)d_in[6];
    const float* pws  = (const float*)d_in[7];
    const float* pbs  = (const float*)d_in[8];
    const float* pwt  = (const float*)d_in[9];
    const float* pbt  = (const float*)d_in[10];
    float* out = (float*)d_out;

    const size_t sm1 = (size_t)(HID * HID + DIN * HID + HID) * sizeof(float);          // ~98.8 KB
    const size_t sm2 = (size_t)(HID * HID + ROWS * SS_LD + HID) * sizeof(float);       // ~98.2 KB

    cudaFuncSetAttribute((const void*)k_spatial,  cudaFuncAttributeMaxDynamicSharedMemorySize, (int)sm1);
    cudaFuncSetAttribute((const void*)k_temporal, cudaFuncAttributeMaxDynamicSharedMemorySize, (int)sm2);

    dim3 g1(N_, 2), g2(BT, 2);
    k_spatial<<<g1, 256, sm1>>>(eb, neb, W1, b1, pws, pbs);
    k_temporal<<<g2, 256, sm2>>>(teb, pwt, pbt, W3, b3, out);
}

// round 7
// speedup vs baseline: 1.5501x; 1.0658x over previous
#include <cuda_runtime.h>

#define B_    32
#define T_    24
#define N_    512
#define BT    768
#define DIN   64
#define HID   128
#define EMB   16
#define DOUT  2
#define ROWS  64
#define NEG   0.01f

#define XS_LD 68
#define SS_LD 132

// Inter-kernel scratch: out_spa [BT, N, HID]
__device__ float g_spa[(size_t)BT * N_ * HID];

__device__ __forceinline__ float lrelu(float x) { return x >= 0.f ? x : NEG * x; }

// ---------------------------------------------------------------------------
// Kernel A (spatial), fused:
//   W_eff[n] = W1 @ W_spa[n];  b_eff[n] = b1 @ W_spa[n] + b_spa[n]
//   out_spa[:, :, n, :] = leaky(eb[:,:,n,:] @ W_eff[n] + b_eff[n])   (K=64)
// ---------------------------------------------------------------------------
__global__ void __launch_bounds__(256, 2)
k_spatial(const float* __restrict__ eb,
          const float* __restrict__ node_eb,
          const float* __restrict__ W1,
          const float* __restrict__ b1,
          const float* __restrict__ pool_w,   // [EMB, HID, HID]
          const float* __restrict__ pool_b)   // [EMB, HID]
{
    extern __shared__ float sm[];
    float* Wsp  = sm;                 // 128x128; later re-used as W_eff (64x128)
    float* W1s  = sm + HID * HID;     // 64x128;  later re-used as xs (64 x XS_LD)
    float* beff = W1s + DIN * HID;    // 128

    const int n = blockIdx.x;
    const int t = threadIdx.x;
    const int rg = t >> 4;   // 16 row groups x 4 rows
    const int cg = t & 15;   // 16 col groups x 8 cols

    float ne[EMB];
#pragma unroll
    for (int d = 0; d < EMB; d++) ne[d] = node_eb[n * EMB + d];

    for (int e = t; e < DIN * HID; e += 256) W1s[e] = W1[e];
    for (int e = t; e < HID * HID; e += 256) {
        float s = 0.f;
#pragma unroll
        for (int d = 0; d < EMB; d++) s += ne[d] * pool_w[d * HID * HID + e];
        Wsp[e] = s;
    }
    __syncthreads();

    // ---- W_eff = W1 @ Wsp  (64x128, K=128), vectorized k-chunks ----
    float acc[4][8];
#pragma unroll
    for (int i = 0; i < 4; i++)
#pragma unroll
        for (int j = 0; j < 8; j++) acc[i][j] = 0.f;

    {
        const float* ar = W1s + (rg * 4) * HID;
        const float* wc = Wsp + cg * 8;
#pragma unroll 2
        for (int k4 = 0; k4 < HID / 4; k4++) {
            float4 av[4];
#pragma unroll
            for (int i = 0; i < 4; i++) av[i] = *(const float4*)(ar + i * HID + k4 * 4);
#pragma unroll
            for (int kk = 0; kk < 4; kk++) {
                float4 w0 = *(const float4*)(wc + (k4 * 4 + kk) * HID);
                float4 w1 = *(const float4*)(wc + (k4 * 4 + kk) * HID + 4);
                float w[8] = {w0.x, w0.y, w0.z, w0.w, w1.x, w1.y, w1.z, w1.w};
#pragma unroll
                for (int i = 0; i < 4; i++) {
                    float a = ((const float*)&av[i])[kk];
#pragma unroll
                    for (int j = 0; j < 8; j++) acc[i][j] += a * w[j];
                }
            }
        }
    }

    // b_eff (reads Wsp: before overwrite)
    if (t < HID) {
        float s = 0.f;
#pragma unroll 8
        for (int k = 0; k < HID; k++) s += b1[k] * Wsp[k * HID + t];
#pragma unroll
        for (int d = 0; d < EMB; d++) s += ne[d] * pool_b[d * HID + t];
        beff[t] = s;
    }
    __syncthreads();   // all Wsp reads complete

#pragma unroll
    for (int i = 0; i < 4; i++) {
        *(float4*)(Wsp + (rg * 4 + i) * HID + cg * 8)     = make_float4(acc[i][0], acc[i][1], acc[i][2], acc[i][3]);
        *(float4*)(Wsp + (rg * 4 + i) * HID + cg * 8 + 4) = make_float4(acc[i][4], acc[i][5], acc[i][6], acc[i][7]);
    }
    float* Weff = Wsp;
    float* xs   = W1s;
    __syncthreads();

    const float* xr = xs + (rg * 4) * XS_LD;
    const float* wc = Weff + cg * 8;

    const int c_base = blockIdx.y * (BT / 2);
    for (int cc = 0; cc < BT / 2; cc += ROWS) {
        const int c0 = c_base + cc;
        for (int f = t; f < ROWS * (DIN / 4); f += 256) {
            int r = f >> 4, q = f & 15;
            float4 v = *(const float4*)(eb + ((size_t)(c0 + r) * N_ + n) * DIN + q * 4);
            *(float4*)(xs + r * XS_LD + q * 4) = v;
        }
        __syncthreads();

        float a2[4][8];
#pragma unroll
        for (int i = 0; i < 4; i++)
#pragma unroll
            for (int j = 0; j < 8; j++) a2[i][j] = beff[cg * 8 + j];

#pragma unroll 2
        for (int k4 = 0; k4 < DIN / 4; k4++) {
            float4 av[4];
#pragma unroll
            for (int i = 0; i < 4; i++) av[i] = *(const float4*)(xr + i * XS_LD + k4 * 4);
#pragma unroll
            for (int kk = 0; kk < 4; kk++) {
                float4 w0 = *(const float4*)(wc + (k4 * 4 + kk) * HID);
                float4 w1 = *(const float4*)(wc + (k4 * 4 + kk) * HID + 4);
                float w[8] = {w0.x, w0.y, w0.z, w0.w, w1.x, w1.y, w1.z, w1.w};
#pragma unroll
                for (int i = 0; i < 4; i++) {
                    float a = ((const float*)&av[i])[kk];
#pragma unroll
                    for (int j = 0; j < 8; j++) a2[i][j] += a * w[j];
                }
            }
        }
#pragma unroll
        for (int i = 0; i < 4; i++) {
            float* dst = g_spa + ((size_t)(c0 + rg * 4 + i) * N_ + n) * HID + cg * 8;
            *(float4*)(dst)     = make_float4(lrelu(a2[i][0]), lrelu(a2[i][1]), lrelu(a2[i][2]), lrelu(a2[i][3]));
            *(float4*)(dst + 4) = make_float4(lrelu(a2[i][4]), lrelu(a2[i][5]), lrelu(a2[i][6]), lrelu(a2[i][7]));
        }
        __syncthreads();
    }
}

// ---------------------------------------------------------------------------
// Kernel B (temporal): one block per (bt, n-half).
//   h = leaky(out_spa[bt] @ W_tem[bt] + b_tem[bt]);  out = h @ W3 + b3
// ---------------------------------------------------------------------------
__global__ void __launch_bounds__(256, 2)
k_temporal(const float* __restrict__ time_eb,
           const float* __restrict__ pool_w,   // [EMB, HID, HID]
           const float* __restrict__ pool_b,   // [EMB, HID]
           const float* __restrict__ W3,       // [HID, DOUT]
           const float* __restrict__ b3,       // [DOUT]
           float* __restrict__ out)
{
    extern __shared__ float sm[];
    float* Wtm = sm;                  // 128x128
    float* ss  = Wtm + HID * HID;     // 64 x SS_LD
    float* btm = ss + ROWS * SS_LD;   // 128

    const int bt = blockIdx.x;
    const int t  = threadIdx.x;
    const int rg = t >> 4;
    const int cg = t & 15;

    float te[EMB];
#pragma unroll
    for (int d = 0; d < EMB; d++) te[d] = time_eb[bt * EMB + d];

    if (t < HID) {
        float s = 0.f;
#pragma unroll
        for (int d = 0; d < EMB; d++) s += te[d] * pool_b[d * HID + t];
        btm[t] = s;
    }
    for (int e = t; e < HID * HID; e += 256) {
        float s = 0.f;
#pragma unroll
        for (int d = 0; d < EMB; d++) s += te[d] * pool_w[d * HID * HID + e];
        Wtm[e] = s;
    }

    float w3r[8][2];
#pragma unroll
    for (int j = 0; j < 8; j++) {
        w3r[j][0] = W3[(cg * 8 + j) * DOUT + 0];
        w3r[j][1] = W3[(cg * 8 + j) * DOUT + 1];
    }
    const float b30 = b3[0], b31 = b3[1];
    __syncthreads();

    const float* sr = ss + (rg * 4) * SS_LD;
    const float* wc = Wtm + cg * 8;

    const int n_base = blockIdx.y * (N_ / 2);
    for (int nn = 0; nn < N_ / 2; nn += ROWS) {
        const int n0 = n_base + nn;
        for (int f = t; f < ROWS * (HID / 4); f += 256) {
            int r = f >> 5, q = f & 31;
            float4 v = *(const float4*)(g_spa + ((size_t)bt * N_ + n0 + r) * HID + q * 4);
            *(float4*)(ss + r * SS_LD + q * 4) = v;
        }
        __syncthreads();

        float acc[4][8];
#pragma unroll
        for (int i = 0; i < 4; i++)
#pragma unroll
            for (int j = 0; j < 8; j++) acc[i][j] = btm[cg * 8 + j];

#pragma unroll 2
        for (int k4 = 0; k4 < HID / 4; k4++) {
            float4 av[4];
#pragma unroll
            for (int i = 0; i < 4; i++) av[i] = *(const float4*)(sr + i * SS_LD + k4 * 4);
#pragma unroll
            for (int kk = 0; kk < 4; kk++) {
                float4 w0 = *(const float4*)(wc + (k4 * 4 + kk) * HID);
                float4 w1 = *(const float4*)(wc + (k4 * 4 + kk) * HID + 4);
                float w[8] = {w0.x, w0.y, w0.z, w0.w, w1.x, w1.y, w1.z, w1.w};
#pragma unroll
                for (int i = 0; i < 4; i++) {
                    float a = ((const float*)&av[i])[kk];
#pragma unroll
                    for (int j = 0; j < 8; j++) acc[i][j] += a * w[j];
                }
            }
        }

        // epilogue: h = leaky(acc); p = h @ W3 partial over this thread's 8 cols
        float p[4][2];
#pragma unroll
        for (int i = 0; i < 4; i++) {
            p[i][0] = 0.f; p[i][1] = 0.f;
#pragma unroll
            for (int j = 0; j < 8; j++) {
                float h = lrelu(acc[i][j]);
                p[i][0] += h * w3r[j][0];
                p[i][1] += h * w3r[j][1];
            }
        }
#pragma unroll
        for (int off = 8; off >= 1; off >>= 1) {
#pragma unroll
            for (int i = 0; i < 4; i++) {
                p[i][0] += __shfl_xor_sync(0xffffffffu, p[i][0], off);
                p[i][1] += __shfl_xor_sync(0xffffffffu, p[i][1], off);
            }
        }
        if (cg == 0) {
#pragma unroll
            for (int i = 0; i < 4; i++) {
                size_t o = ((size_t)bt * N_ + n0 + rg * 4 + i) * DOUT;
                out[o + 0] = p[i][0] + b30;
                out[o + 1] = p[i][1] + b31;
            }
        }
        __syncthreads();
    }
}

// ---------------------------------------------------------------------------
extern "C" void kernel_launch(void* const* d_in, const int* in_sizes, int n_in,
                              void* d_out, int out_size)
{
    const float* eb   = (const float*)d_in[0];
    const float* teb  = (const float*)d_in[1];
    const float* neb  = (const float*)d_in[2];
    const float* W1   = (const float*)d_in[3];
    const float* b1   = (const float*)d_in[4];
    const float* W3   = (const float*)d_in[5];
    const float* b3   = (const float*)d_in[6];
    const float* pws  = (const float*)d_in[7];
    const float* pbs  = (const float*)d_in[8];
    const float* pwt  = (const float*)d_in[9];
    const float* pbt  = (const float*)d_in[10];
    float* out = (float*)d_out;

    const size_t sm1 = (size_t)(HID * HID + DIN * HID + HID) * sizeof(float);
    const size_t sm2 = (size_t)(HID * HID + ROWS * SS_LD + HID) * sizeof(float);

    cudaFuncSetAttribute((const void*)k_spatial,  cudaFuncAttributeMaxDynamicSharedMemorySize, (int)sm1);
    cudaFuncSetAttribute((const void*)k_temporal, cudaFuncAttributeMaxDynamicSharedMemorySize, (int)sm2);

    dim3 g1(N_, 2), g2(BT, 2);
    k_spatial<<<g1, 256, sm1>>>(eb, neb, W1, b1, pws, pbs);
    k_temporal<<<g2, 256, sm2>>>(teb, pwt, pbt, W3, b3, out);
}

// round 9
// speedup vs baseline: 2.1376x; 1.3790x over previous
#include <cuda_runtime.h>
#include <cuda_bf16.h>
#include <cstdint>

#define B_    32
#define T_    24
#define N_    512
#define BT    768
#define DIN   64
#define HID   128
#define EMB   16
#define DOUT  2
#define ROWS  64
#define NEG   0.01f

#define XS_LD 68

// Inter-kernel scratch: out_spa split into bf16 hi/lo, [BT, N, HID] each
__device__ __nv_bfloat16 g_hi[(size_t)BT * N_ * HID];
__device__ __nv_bfloat16 g_lo[(size_t)BT * N_ * HID];

__device__ __forceinline__ float lrelu(float x) { return x >= 0.f ? x : NEG * x; }

__device__ __forceinline__ uint32_t smem_u32(const void* p) {
    uint32_t a;
    asm("{ .reg .u64 t; cvta.to.shared.u64 t, %1; cvt.u32.u64 %0, t; }" : "=r"(a) : "l"(p));
    return a;
}
__device__ __forceinline__ void ldsm_x4(uint32_t* r, uint32_t addr) {
    asm volatile("ldmatrix.sync.aligned.m8n8.x4.shared.b16 {%0,%1,%2,%3}, [%4];"
                 : "=r"(r[0]), "=r"(r[1]), "=r"(r[2]), "=r"(r[3]) : "r"(addr));
}
__device__ __forceinline__ void mma_bf16(float* d, const uint32_t* a, uint32_t b0, uint32_t b1) {
    asm volatile("mma.sync.aligned.m16n8k16.row.col.f32.bf16.bf16.f32 "
                 "{%0,%1,%2,%3}, {%4,%5,%6,%7}, {%8,%9}, {%0,%1,%2,%3};"
                 : "+f"(d[0]), "+f"(d[1]), "+f"(d[2]), "+f"(d[3])
                 : "r"(a[0]), "r"(a[1]), "r"(a[2]), "r"(a[3]), "r"(b0), "r"(b1));
}

// ---------------------------------------------------------------------------
// Kernel A (spatial), CUDA cores: W_eff = W1@W_spa fusion; emits bf16 hi/lo.
// ---------------------------------------------------------------------------
__global__ void __launch_bounds__(256, 2)
k_spatial(const float* __restrict__ eb,
          const float* __restrict__ node_eb,
          const float* __restrict__ W1,
          const float* __restrict__ b1,
          const float* __restrict__ pool_w,
          const float* __restrict__ pool_b)
{
    extern __shared__ float sm[];
    float* Wsp  = sm;                 // 128x128; later W_eff (64x128)
    float* W1s  = sm + HID * HID;     // 64x128;  later xs
    float* beff = W1s + DIN * HID;    // 128

    const int n = blockIdx.x;
    const int t = threadIdx.x;
    const int rg = t >> 4;
    const int cg = t & 15;

    float ne[EMB];
#pragma unroll
    for (int d = 0; d < EMB; d++) ne[d] = node_eb[n * EMB + d];

    for (int e = t; e < DIN * HID; e += 256) W1s[e] = W1[e];
    for (int e = t; e < HID * HID; e += 256) {
        float s = 0.f;
#pragma unroll
        for (int d = 0; d < EMB; d++) s += ne[d] * pool_w[d * HID * HID + e];
        Wsp[e] = s;
    }
    __syncthreads();

    float acc[4][8];
#pragma unroll
    for (int i = 0; i < 4; i++)
#pragma unroll
        for (int j = 0; j < 8; j++) acc[i][j] = 0.f;
    {
        const float* ar = W1s + (rg * 4) * HID;
        const float* wcp = Wsp + cg * 8;
#pragma unroll 2
        for (int k4 = 0; k4 < HID / 4; k4++) {
            float4 av[4];
#pragma unroll
            for (int i = 0; i < 4; i++) av[i] = *(const float4*)(ar + i * HID + k4 * 4);
#pragma unroll
            for (int kk = 0; kk < 4; kk++) {
                float4 w0 = *(const float4*)(wcp + (k4 * 4 + kk) * HID);
                float4 w1 = *(const float4*)(wcp + (k4 * 4 + kk) * HID + 4);
                float w[8] = {w0.x, w0.y, w0.z, w0.w, w1.x, w1.y, w1.z, w1.w};
#pragma unroll
                for (int i = 0; i < 4; i++) {
                    float a = ((const float*)&av[i])[kk];
#pragma unroll
                    for (int j = 0; j < 8; j++) acc[i][j] += a * w[j];
                }
            }
        }
    }

    if (t < HID) {
        float s = 0.f;
#pragma unroll 8
        for (int k = 0; k < HID; k++) s += b1[k] * Wsp[k * HID + t];
#pragma unroll
        for (int d = 0; d < EMB; d++) s += ne[d] * pool_b[d * HID + t];
        beff[t] = s;
    }
    __syncthreads();

#pragma unroll
    for (int i = 0; i < 4; i++) {
        *(float4*)(Wsp + (rg * 4 + i) * HID + cg * 8)     = make_float4(acc[i][0], acc[i][1], acc[i][2], acc[i][3]);
        *(float4*)(Wsp + (rg * 4 + i) * HID + cg * 8 + 4) = make_float4(acc[i][4], acc[i][5], acc[i][6], acc[i][7]);
    }
    float* Weff = Wsp;
    float* xs   = W1s;
    __syncthreads();

    const float* xr = xs + (rg * 4) * XS_LD;
    const float* wcp = Weff + cg * 8;

    const int c_base = blockIdx.y * (BT / 2);
    for (int cc = 0; cc < BT / 2; cc += ROWS) {
        const int c0 = c_base + cc;
        for (int f = t; f < ROWS * (DIN / 4); f += 256) {
            int r = f >> 4, q = f & 15;
            float4 v = *(const float4*)(eb + ((size_t)(c0 + r) * N_ + n) * DIN + q * 4);
            *(float4*)(xs + r * XS_LD + q * 4) = v;
        }
        __syncthreads();

        float a2[4][8];
#pragma unroll
        for (int i = 0; i < 4; i++)
#pragma unroll
            for (int j = 0; j < 8; j++) a2[i][j] = beff[cg * 8 + j];

#pragma unroll 2
        for (int k4 = 0; k4 < DIN / 4; k4++) {
            float4 av[4];
#pragma unroll
            for (int i = 0; i < 4; i++) av[i] = *(const float4*)(xr + i * XS_LD + k4 * 4);
#pragma unroll
            for (int kk = 0; kk < 4; kk++) {
                float4 w0 = *(const float4*)(wcp + (k4 * 4 + kk) * HID);
                float4 w1 = *(const float4*)(wcp + (k4 * 4 + kk) * HID + 4);
                float w[8] = {w0.x, w0.y, w0.z, w0.w, w1.x, w1.y, w1.z, w1.w};
#pragma unroll
                for (int i = 0; i < 4; i++) {
                    float a = ((const float*)&av[i])[kk];
#pragma unroll
                    for (int j = 0; j < 8; j++) a2[i][j] += a * w[j];
                }
            }
        }
#pragma unroll
        for (int i = 0; i < 4; i++) {
            __nv_bfloat16 hv[8], lv[8];
#pragma unroll
            for (int j = 0; j < 8; j++) {
                float h = lrelu(a2[i][j]);
                hv[j] = __float2bfloat16(h);
                lv[j] = __float2bfloat16(h - __bfloat162float(hv[j]));
            }
            size_t idx = ((size_t)(c0 + rg * 4 + i) * N_ + n) * HID + cg * 8;
            *(uint4*)(g_hi + idx) = *(uint4*)hv;
            *(uint4*)(g_lo + idx) = *(uint4*)lv;
        }
        __syncthreads();
    }
}

// ---------------------------------------------------------------------------
// Kernel B (temporal), mma.sync bf16 hi/lo: one block per bt.
//   D = A_hi@B_hi + A_lo@B_hi + A_hi@B_lo (fp32 accum)
//   epilogue: h = leaky(D + btm); out = h @ W3 + b3  (shfl + smem-atomic reduce)
//
// smem (bytes):
//   [0    ) btm    512
//   [512  ) W3s   1024
//   [1536 ) pout   512
//   [2048 ) B_HI  34816  (128 rows x 272B)
//   [36864) B_LO  34816
//   [71680) A_HI  17408  (64 rows x 272B)
//   [89088) A_LO  17408
//   total 106496 -> 2 CTA/SM
// ---------------------------------------------------------------------------
#define TLD   272           // padded row stride in bytes (136 halves)
#define SMB_BTM  0
#define SMB_W3   512
#define SMB_POUT 1536
#define SMB_BHI  2048
#define SMB_BLO  36864
#define SMB_AHI  71680
#define SMB_ALO  89088
#define SMB_TOT  106496

__global__ void __launch_bounds__(256, 2)
k_temporal(const float* __restrict__ time_eb,
           const float* __restrict__ pool_w,   // [EMB, HID(in=i), HID(out=o)]
           const float* __restrict__ pool_b,   // [EMB, HID]
           const float* __restrict__ W3,       // [HID, DOUT]
           const float* __restrict__ b3,       // [DOUT]
           float* __restrict__ out)
{
    extern __shared__ char smch[];
    const uint32_t smb = smem_u32(smch);
    float* btm  = (float*)(smch + SMB_BTM);
    float* W3s  = (float*)(smch + SMB_W3);
    float* pout = (float*)(smch + SMB_POUT);

    const int bt  = blockIdx.x;
    const int t   = threadIdx.x;
    const int wid = t >> 5;
    const int l   = t & 31;

    float te[EMB];
#pragma unroll
    for (int d = 0; d < EMB; d++) te[d] = time_eb[bt * EMB + d];

    if (t < HID) {
        float s = 0.f;
#pragma unroll
        for (int d = 0; d < EMB; d++) s += te[d] * pool_b[d * HID + t];
        btm[t] = s;
    }
    if (t < HID * DOUT) W3s[t] = W3[t];

    // --- generate B = W_tem^T as bf16 hi/lo: B[o][i], row stride TLD ---
    {
        const int kq = t >> 5;        // i sub-index (0..7)
        const int c4 = (t & 31) * 4;  // 4 consecutive o's
#pragma unroll 1
        for (int pass = 0; pass < 16; pass++) {
            const int k = kq + pass * 8;   // i
            float4 a = make_float4(0.f, 0.f, 0.f, 0.f);
#pragma unroll
            for (int d = 0; d < EMB; d++) {
                float4 p = *(const float4*)(pool_w + (size_t)d * HID * HID + k * HID + c4);
                a.x += te[d] * p.x; a.y += te[d] * p.y; a.z += te[d] * p.z; a.w += te[d] * p.w;
            }
            const float av[4] = {a.x, a.y, a.z, a.w};
#pragma unroll
            for (int j = 0; j < 4; j++) {
                const int c = c4 + j;   // o (row)
                float x = av[j];
                __nv_bfloat16 hi = __float2bfloat16(x);
                __nv_bfloat16 lo = __float2bfloat16(x - __bfloat162float(hi));
                *(__nv_bfloat16*)(smch + SMB_BHI + c * TLD + k * 2) = hi;
                *(__nv_bfloat16*)(smch + SMB_BLO + c * TLD + k * 2) = lo;
            }
        }
    }

    // warp tiling: 2 M-warps x 4 N-warps over a 64x128 tile
    const int mw = wid & 1;          // 0..1 -> 32 rows
    const int nw = wid >> 1;         // 0..3 -> 32 cols
    const int m0w = mw * 32;
    const int n0w = nw * 32;
    const int g  = l >> 2;
    const int tq = l & 3;

    // per-lane ldmatrix address offsets (bytes)
    const uint32_t aoff = (uint32_t)(((l & 7) + ((l >> 3) & 1) * 8) * TLD + ((l >> 4) & 1) * 16);
    const uint32_t boff = (uint32_t)(((l & 7) + ((l >> 4) & 1) * 8) * TLD + ((l >> 3) & 1) * 16);

    const uint32_t APASS[3] = {SMB_AHI, SMB_ALO, SMB_AHI};
    const uint32_t BPASS[3] = {SMB_BHI, SMB_BHI, SMB_BLO};
    const float b30 = __ldg(b3), b31 = __ldg(b3 + 1);

    __syncthreads();   // B / btm / W3s ready

#pragma unroll 1
    for (int tile = 0; tile < 8; tile++) {
        const int r0 = tile * 64;

        // load A tile (64 rows x 128 halves, hi+lo) + init pout
#pragma unroll
        for (int i = 0; i < 4; i++) {
            int chunk = t + i * 256;           // 0..1023
            int r = chunk >> 4, k16 = chunk & 15;
            size_t src = ((size_t)bt * N_ + r0 + r) * HID + k16 * 8;
            *(uint4*)(smch + SMB_AHI + r * TLD + k16 * 16) = *(const uint4*)(g_hi + src);
            *(uint4*)(smch + SMB_ALO + r * TLD + k16 * 16) = *(const uint4*)(g_lo + src);
        }
        if (t < 128) pout[t] = (t & 1) ? b31 : b30;
        __syncthreads();

        // --- MMA: 3 passes x 8 k-chunks ---
        float acc[2][4][4];
#pragma unroll
        for (int mi = 0; mi < 2; mi++)
#pragma unroll
            for (int nj = 0; nj < 4; nj++)
#pragma unroll
                for (int q = 0; q < 4; q++) acc[mi][nj][q] = 0.f;

#pragma unroll 1
        for (int p = 0; p < 3; p++) {
            const uint32_t Ab = smb + APASS[p] + (uint32_t)m0w * TLD + aoff;
            const uint32_t Bb = smb + BPASS[p] + (uint32_t)n0w * TLD + boff;
#pragma unroll 4
            for (int kc = 0; kc < 8; kc++) {
                uint32_t a0[4], a1[4], bA[4], bB[4];
                ldsm_x4(a0, Ab + kc * 32);
                ldsm_x4(a1, Ab + 16 * TLD + kc * 32);
                ldsm_x4(bA, Bb + kc * 32);
                ldsm_x4(bB, Bb + 16 * TLD + kc * 32);
                mma_bf16(acc[0][0], a0, bA[0], bA[1]);
                mma_bf16(acc[0][1], a0, bA[2], bA[3]);
                mma_bf16(acc[0][2], a0, bB[0], bB[1]);
                mma_bf16(acc[0][3], a0, bB[2], bB[3]);
                mma_bf16(acc[1][0], a1, bA[0], bA[1]);
                mma_bf16(acc[1][1], a1, bA[2], bA[3]);
                mma_bf16(acc[1][2], a1, bB[0], bB[1]);
                mma_bf16(acc[1][3], a1, bB[2], bB[3]);
            }
        }

        // --- epilogue: h = leaky(D + btm); partial @W3; reduce ---
#pragma unroll
        for (int mi = 0; mi < 2; mi++) {
#pragma unroll
            for (int rh = 0; rh < 2; rh++) {
                int rowl = m0w + 16 * mi + 8 * rh + g;
                float p0 = 0.f, p1 = 0.f;
#pragma unroll
                for (int nj = 0; nj < 4; nj++) {
                    int col = n0w + 8 * nj + 2 * tq;
                    float h0 = lrelu(acc[mi][nj][rh * 2 + 0] + btm[col]);
                    float h1 = lrelu(acc[mi][nj][rh * 2 + 1] + btm[col + 1]);
                    p0 += h0 * W3s[col * 2 + 0] + h1 * W3s[(col + 1) * 2 + 0];
                    p1 += h0 * W3s[col * 2 + 1] + h1 * W3s[(col + 1) * 2 + 1];
                }
                p0 += __shfl_xor_sync(0xffffffffu, p0, 1);
                p1 += __shfl_xor_sync(0xffffffffu, p1, 1);
                p0 += __shfl_xor_sync(0xffffffffu, p0, 2);
                p1 += __shfl_xor_sync(0xffffffffu, p1, 2);
                if (tq == 0) {
                    atomicAdd(&pout[rowl * 2 + 0], p0);
                    atomicAdd(&pout[rowl * 2 + 1], p1);
                }
            }
        }
        __syncthreads();

        if (t < 128) out[((size_t)bt * N_ + r0) * DOUT + t] = pout[t];
        __syncthreads();   // pout/A consumed before next tile
    }
}

// ---------------------------------------------------------------------------
extern "C" void kernel_launch(void* const* d_in, const int* in_sizes, int n_in,
                              void* d_out, int out_size)
{
    const float* eb   = (const float*)d_in[0];
    const float* teb  = (const float*)d_in[1];
    const float* neb  = (const float*)d_in[2];
    const float* W1   = (const float*)d_in[3];
    const float* b1   = (const float*)d_in[4];
    const float* W3   = (const float*)d_in[5];
    const float* b3   = (const float*)d_in[6];
    const float* pws  = (const float*)d_in[7];
    const float* pbs  = (const float*)d_in[8];
    const float* pwt  = (const float*)d_in[9];
    const float* pbt  = (const float*)d_in[10];
    float* out = (float*)d_out;

    const size_t sm1 = (size_t)(HID * HID + DIN * HID + HID) * sizeof(float);

    cudaFuncSetAttribute((const void*)k_spatial,  cudaFuncAttributeMaxDynamicSharedMemorySize, (int)sm1);
    cudaFuncSetAttribute((const void*)k_temporal, cudaFuncAttributeMaxDynamicSharedMemorySize, SMB_TOT);

    dim3 g1(N_, 2);
    k_spatial<<<g1, 256, sm1>>>(eb, neb, W1, b1, pws, pbs);
    k_temporal<<<BT, 256, SMB_TOT>>>(teb, pwt, pbt, W3, b3, out);
}

// round 11
// speedup vs baseline: 3.9789x; 1.8614x over previous
#include <cuda_runtime.h>
#include <cuda_bf16.h>
#include <cstdint>

#define B_    32
#define T_    24
#define N_    512
#define BT    768
#define DIN   64
#define HID   128
#define EMB   16
#define DOUT  2
#define NEG   0.01f

// Inter-kernel scratch: out_spa split into bf16 hi/lo, [BT, N, HID] each
__device__ __nv_bfloat16 g_hi[(size_t)BT * N_ * HID];
__device__ __nv_bfloat16 g_lo[(size_t)BT * N_ * HID];
// Precomputed: P[d] = W1 @ pool_w_spa[d]  (64x128 each), pbe[d] = b1@pool_w_spa[d] + pool_b_spa[d]
__device__ float g_P[(size_t)EMB * DIN * HID];
__device__ float g_pbe[(size_t)EMB * HID];

__device__ __forceinline__ float lrelu(float x) { return x >= 0.f ? x : NEG * x; }

__device__ __forceinline__ uint32_t smem_u32(const void* p) {
    uint32_t a;
    asm("{ .reg .u64 t; cvta.to.shared.u64 t, %1; cvt.u32.u64 %0, t; }" : "=r"(a) : "l"(p));
    return a;
}
__device__ __forceinline__ void ldsm_x4(uint32_t* r, uint32_t addr) {
    asm volatile("ldmatrix.sync.aligned.m8n8.x4.shared.b16 {%0,%1,%2,%3}, [%4];"
                 : "=r"(r[0]), "=r"(r[1]), "=r"(r[2]), "=r"(r[3]) : "r"(addr));
}
__device__ __forceinline__ void mma_bf16(float* d, const uint32_t* a, uint32_t b0, uint32_t b1) {
    asm volatile("mma.sync.aligned.m16n8k16.row.col.f32.bf16.bf16.f32 "
                 "{%0,%1,%2,%3}, {%4,%5,%6,%7}, {%8,%9}, {%0,%1,%2,%3};"
                 : "+f"(d[0]), "+f"(d[1]), "+f"(d[2]), "+f"(d[3])
                 : "r"(a[0]), "r"(a[1]), "r"(a[2]), "r"(a[3]), "r"(b0), "r"(b1));
}
__device__ __forceinline__ uint32_t pack_bf16_hi(float a, float b) {
    __nv_bfloat16 ha = __float2bfloat16(a), hb = __float2bfloat16(b);
    return (uint32_t)*(uint16_t*)&ha | ((uint32_t)*(uint16_t*)&hb << 16);
}

// ---------------------------------------------------------------------------
// Kernel P (precompute): one block per d.
//   g_P[d]   = W1 @ pool_w_spa[d]        (64x128, K=128)
//   g_pbe[d] = b1 @ pool_w_spa[d] + pool_b_spa[d]
// ---------------------------------------------------------------------------
__global__ void __launch_bounds__(256)
k_pre(const float* __restrict__ W1, const float* __restrict__ b1,
      const float* __restrict__ pool_w, const float* __restrict__ pool_b)
{
    extern __shared__ float sp[];
    float* W1s = sp;                  // 64x128
    float* Pl  = sp + DIN * HID;      // 128x128

    const int d = blockIdx.x;
    const int t = threadIdx.x;
    const int rg = t >> 4, cg = t & 15;

    for (int e = t; e < DIN * HID; e += 256) W1s[e] = W1[e];
    for (int e = t; e < HID * HID; e += 256) Pl[e] = pool_w[(size_t)d * HID * HID + e];
    __syncthreads();

    float acc[4][8];
#pragma unroll
    for (int i = 0; i < 4; i++)
#pragma unroll
        for (int j = 0; j < 8; j++) acc[i][j] = 0.f;

    const float* ar = W1s + (rg * 4) * HID;
    const float* wc = Pl + cg * 8;
#pragma unroll 2
    for (int k4 = 0; k4 < HID / 4; k4++) {
        float4 av[4];
#pragma unroll
        for (int i = 0; i < 4; i++) av[i] = *(const float4*)(ar + i * HID + k4 * 4);
#pragma unroll
        for (int kk = 0; kk < 4; kk++) {
            float4 w0 = *(const float4*)(wc + (k4 * 4 + kk) * HID);
            float4 w1 = *(const float4*)(wc + (k4 * 4 + kk) * HID + 4);
            float w[8] = {w0.x, w0.y, w0.z, w0.w, w1.x, w1.y, w1.z, w1.w};
#pragma unroll
            for (int i = 0; i < 4; i++) {
                float a = ((const float*)&av[i])[kk];
#pragma unroll
                for (int j = 0; j < 8; j++) acc[i][j] += a * w[j];
            }
        }
    }
#pragma unroll
    for (int i = 0; i < 4; i++)
#pragma unroll
        for (int j = 0; j < 8; j++)
            g_P[(size_t)d * DIN * HID + (rg * 4 + i) * HID + cg * 8 + j] = acc[i][j];

    if (t < HID) {
        float s = pool_b[d * HID + t];
#pragma unroll 8
        for (int k = 0; k < HID; k++) s += b1[k] * Pl[k * HID + t];
        g_pbe[d * HID + t] = s;
    }
}

// ---------------------------------------------------------------------------
// Kernel A (spatial), mma.sync bf16 hi/lo: one block per (node, bt-half).
//   W_eff = sum_d ne[d] * g_P[d]  (64x128, generated hi/lo into smem)
//   out_spa = leaky(x @ W_eff + b_eff), x hi/lo split on load; 3-pass MMA.
// smem: [bsp 512][B_HI 18432][B_LO 18432][A_HI 9216][A_LO 9216] = 55808 B
// ---------------------------------------------------------------------------
#define SLD     144
#define SP_BSP  0
#define SP_BHI  512
#define SP_BLO  18944
#define SP_AHI  37376
#define SP_ALO  46592
#define SP_TOT  55808

__global__ void __launch_bounds__(256)
k_spatial(const float* __restrict__ eb, const float* __restrict__ node_eb)
{
    extern __shared__ char smch[];
    const uint32_t smb = smem_u32(smch);
    float* bsp = (float*)(smch + SP_BSP);

    const int n   = blockIdx.x;
    const int t   = threadIdx.x;
    const int wid = t >> 5;
    const int l   = t & 31;

    float ne[EMB];
#pragma unroll
    for (int d = 0; d < EMB; d++) ne[d] = node_eb[n * EMB + d];

    // --- generate B = W_eff^T hi/lo: row = o (0..127), col = k (0..63) ---
    for (int e = t; e < DIN * HID; e += 256) {
        float s = 0.f;
#pragma unroll
        for (int d = 0; d < EMB; d++) s += ne[d] * g_P[(size_t)d * DIN * HID + e];
        const int r = e >> 7, o = e & 127;   // r = input dim (k), o = output
        __nv_bfloat16 hi = __float2bfloat16(s);
        __nv_bfloat16 lo = __float2bfloat16(s - __bfloat162float(hi));
        *(__nv_bfloat16*)(smch + SP_BHI + o * SLD + r * 2) = hi;
        *(__nv_bfloat16*)(smch + SP_BLO + o * SLD + r * 2) = lo;
    }
    if (t < HID) {
        float s = 0.f;
#pragma unroll
        for (int d = 0; d < EMB; d++) s += ne[d] * g_pbe[d * HID + t];
        bsp[t] = s;
    }

    const int mw = wid & 1, nw = wid >> 1;
    const int m0w = mw * 32, n0w = nw * 32;
    const int g  = l >> 2, tq = l & 3;
    const uint32_t aoff = (uint32_t)(((l & 7) + ((l >> 3) & 1) * 8) * SLD + ((l >> 4) & 1) * 16);
    const uint32_t boff = (uint32_t)(((l & 7) + ((l >> 4) & 1) * 8) * SLD + ((l >> 3) & 1) * 16);
    const uint32_t APASS[3] = {SP_AHI, SP_ALO, SP_AHI};
    const uint32_t BPASS[3] = {SP_BHI, SP_BHI, SP_BLO};

    __syncthreads();

    const int c_base = blockIdx.y * (BT / 2);
#pragma unroll 1
    for (int tt = 0; tt < BT / 2; tt += 64) {
        const int c0 = c_base + tt;

        // --- load x tile [64 x 64] fp32, split hi/lo into smem ---
#pragma unroll
        for (int i = 0; i < 4; i++) {
            int chunk = t + i * 256;          // 0..1023 = 64 rows x 16 float4
            int r = chunk >> 4, q = chunk & 15;
            float4 v = *(const float4*)(eb + ((size_t)(c0 + r) * N_ + n) * DIN + q * 4);
            __nv_bfloat16 h0 = __float2bfloat16(v.x), h1 = __float2bfloat16(v.y);
            __nv_bfloat16 h2 = __float2bfloat16(v.z), h3 = __float2bfloat16(v.w);
            uint2 uh, ul;
            uh.x = (uint32_t)*(uint16_t*)&h0 | ((uint32_t)*(uint16_t*)&h1 << 16);
            uh.y = (uint32_t)*(uint16_t*)&h2 | ((uint32_t)*(uint16_t*)&h3 << 16);
            ul.x = pack_bf16_hi(v.x - __bfloat162float(h0), v.y - __bfloat162float(h1));
            ul.y = pack_bf16_hi(v.z - __bfloat162float(h2), v.w - __bfloat162float(h3));
            *(uint2*)(smch + SP_AHI + r * SLD + q * 8) = uh;
            *(uint2*)(smch + SP_ALO + r * SLD + q * 8) = ul;
        }
        __syncthreads();

        float acc[2][4][4];
#pragma unroll
        for (int mi = 0; mi < 2; mi++)
#pragma unroll
            for (int nj = 0; nj < 4; nj++)
#pragma unroll
                for (int q = 0; q < 4; q++) acc[mi][nj][q] = 0.f;

#pragma unroll 1
        for (int p = 0; p < 3; p++) {
            const uint32_t Ab = smb + APASS[p] + (uint32_t)m0w * SLD + aoff;
            const uint32_t Bb = smb + BPASS[p] + (uint32_t)n0w * SLD + boff;
#pragma unroll
            for (int kc = 0; kc < 4; kc++) {
                uint32_t a0[4], a1[4], bA[4], bB[4];
                ldsm_x4(a0, Ab + kc * 32);
                ldsm_x4(a1, Ab + 16 * SLD + kc * 32);
                ldsm_x4(bA, Bb + kc * 32);
                ldsm_x4(bB, Bb + 16 * SLD + kc * 32);
                mma_bf16(acc[0][0], a0, bA[0], bA[1]);
                mma_bf16(acc[0][1], a0, bA[2], bA[3]);
                mma_bf16(acc[0][2], a0, bB[0], bB[1]);
                mma_bf16(acc[0][3], a0, bB[2], bB[3]);
                mma_bf16(acc[1][0], a1, bA[0], bA[1]);
                mma_bf16(acc[1][1], a1, bA[2], bA[3]);
                mma_bf16(acc[1][2], a1, bB[0], bB[1]);
                mma_bf16(acc[1][3], a1, bB[2], bB[3]);
            }
        }

        // --- epilogue: + b_eff, leaky, hi/lo bf16, store to g_hi/g_lo ---
#pragma unroll
        for (int mi = 0; mi < 2; mi++) {
#pragma unroll
            for (int rh = 0; rh < 2; rh++) {
                const int row = m0w + 16 * mi + 8 * rh + g;
                const size_t base = ((size_t)(c0 + row) * N_ + n) * HID;
#pragma unroll
                for (int nj = 0; nj < 4; nj++) {
                    const int col = n0w + 8 * nj + 2 * tq;
                    float h0 = lrelu(acc[mi][nj][rh * 2 + 0] + bsp[col]);
                    float h1 = lrelu(acc[mi][nj][rh * 2 + 1] + bsp[col + 1]);
                    __nv_bfloat16 a = __float2bfloat16(h0), b = __float2bfloat16(h1);
                    uint32_t hp = (uint32_t)*(uint16_t*)&a | ((uint32_t)*(uint16_t*)&b << 16);
                    uint32_t lp = pack_bf16_hi(h0 - __bfloat162float(a), h1 - __bfloat162float(b));
                    *(uint32_t*)(g_hi + base + col) = hp;
                    *(uint32_t*)(g_lo + base + col) = lp;
                }
            }
        }
        __syncthreads();   // A smem consumed before next tile load
    }
}

// ---------------------------------------------------------------------------
// Kernel B (temporal), mma.sync bf16 hi/lo (unchanged from R9).
// ---------------------------------------------------------------------------
#define TLD   272
#define SMB_BTM  0
#define SMB_W3   512
#define SMB_POUT 1536
#define SMB_BHI  2048
#define SMB_BLO  36864
#define SMB_AHI  71680
#define SMB_ALO  89088
#define SMB_TOT  106496

__global__ void __launch_bounds__(256, 2)
k_temporal(const float* __restrict__ time_eb,
           const float* __restrict__ pool_w,
           const float* __restrict__ pool_b,
           const float* __restrict__ W3,
           const float* __restrict__ b3,
           float* __restrict__ out)
{
    extern __shared__ char smch[];
    const uint32_t smb = smem_u32(smch);
    float* btm  = (float*)(smch + SMB_BTM);
    float* W3s  = (float*)(smch + SMB_W3);
    float* pout = (float*)(smch + SMB_POUT);

    const int bt  = blockIdx.x;
    const int t   = threadIdx.x;
    const int wid = t >> 5;
    const int l   = t & 31;

    float te[EMB];
#pragma unroll
    for (int d = 0; d < EMB; d++) te[d] = time_eb[bt * EMB + d];

    if (t < HID) {
        float s = 0.f;
#pragma unroll
        for (int d = 0; d < EMB; d++) s += te[d] * pool_b[d * HID + t];
        btm[t] = s;
    }
    if (t < HID * DOUT) W3s[t] = W3[t];

    {
        const int kq = t >> 5;
        const int c4 = (t & 31) * 4;
#pragma unroll 1
        for (int pass = 0; pass < 16; pass++) {
            const int k = kq + pass * 8;
            float4 a = make_float4(0.f, 0.f, 0.f, 0.f);
#pragma unroll
            for (int d = 0; d < EMB; d++) {
                float4 p = *(const float4*)(pool_w + (size_t)d * HID * HID + k * HID + c4);
                a.x += te[d] * p.x; a.y += te[d] * p.y; a.z += te[d] * p.z; a.w += te[d] * p.w;
            }
            const float av[4] = {a.x, a.y, a.z, a.w};
#pragma unroll
            for (int j = 0; j < 4; j++) {
                const int c = c4 + j;
                float x = av[j];
                __nv_bfloat16 hi = __float2bfloat16(x);
                __nv_bfloat16 lo = __float2bfloat16(x - __bfloat162float(hi));
                *(__nv_bfloat16*)(smch + SMB_BHI + c * TLD + k * 2) = hi;
                *(__nv_bfloat16*)(smch + SMB_BLO + c * TLD + k * 2) = lo;
            }
        }
    }

    const int mw = wid & 1, nw = wid >> 1;
    const int m0w = mw * 32, n0w = nw * 32;
    const int g  = l >> 2, tq = l & 3;
    const uint32_t aoff = (uint32_t)(((l & 7) + ((l >> 3) & 1) * 8) * TLD + ((l >> 4) & 1) * 16);
    const uint32_t boff = (uint32_t)(((l & 7) + ((l >> 4) & 1) * 8) * TLD + ((l >> 3) & 1) * 16);
    const uint32_t APASS[3] = {SMB_AHI, SMB_ALO, SMB_AHI};
    const uint32_t BPASS[3] = {SMB_BHI, SMB_BHI, SMB_BLO};
    const float b30 = __ldg(b3), b31 = __ldg(b3 + 1);

    __syncthreads();

#pragma unroll 1
    for (int tile = 0; tile < 8; tile++) {
        const int r0 = tile * 64;

#pragma unroll
        for (int i = 0; i < 4; i++) {
            int chunk = t + i * 256;
            int r = chunk >> 4, k16 = chunk & 15;
            size_t src = ((size_t)bt * N_ + r0 + r) * HID + k16 * 8;
            *(uint4*)(smch + SMB_AHI + r * TLD + k16 * 16) = *(const uint4*)(g_hi + src);
            *(uint4*)(smch + SMB_ALO + r * TLD + k16 * 16) = *(const uint4*)(g_lo + src);
        }
        if (t < 128) pout[t] = (t & 1) ? b31 : b30;
        __syncthreads();

        float acc[2][4][4];
#pragma unroll
        for (int mi = 0; mi < 2; mi++)
#pragma unroll
            for (int nj = 0; nj < 4; nj++)
#pragma unroll
                for (int q = 0; q < 4; q++) acc[mi][nj][q] = 0.f;

#pragma unroll 1
        for (int p = 0; p < 3; p++) {
            const uint32_t Ab = smb + APASS[p] + (uint32_t)m0w * TLD + aoff;
            const uint32_t Bb = smb + BPASS[p] + (uint32_t)n0w * TLD + boff;
#pragma unroll 4
            for (int kc = 0; kc < 8; kc++) {
                uint32_t a0[4], a1[4], bA[4], bB[4];
                ldsm_x4(a0, Ab + kc * 32);
                ldsm_x4(a1, Ab + 16 * TLD + kc * 32);
                ldsm_x4(bA, Bb + kc * 32);
                ldsm_x4(bB, Bb + 16 * TLD + kc * 32);
                mma_bf16(acc[0][0], a0, bA[0], bA[1]);
                mma_bf16(acc[0][1], a0, bA[2], bA[3]);
                mma_bf16(acc[0][2], a0, bB[0], bB[1]);
                mma_bf16(acc[0][3], a0, bB[2], bB[3]);
                mma_bf16(acc[1][0], a1, bA[0], bA[1]);
                mma_bf16(acc[1][1], a1, bA[2], bA[3]);
                mma_bf16(acc[1][2], a1, bB[0], bB[1]);
                mma_bf16(acc[1][3], a1, bB[2], bB[3]);
            }
        }

#pragma unroll
        for (int mi = 0; mi < 2; mi++) {
#pragma unroll
            for (int rh = 0; rh < 2; rh++) {
                int rowl = m0w + 16 * mi + 8 * rh + g;
                float p0 = 0.f, p1 = 0.f;
#pragma unroll
                for (int nj = 0; nj < 4; nj++) {
                    int col = n0w + 8 * nj + 2 * tq;
                    float h0 = lrelu(acc[mi][nj][rh * 2 + 0] + btm[col]);
                    float h1 = lrelu(acc[mi][nj][rh * 2 + 1] + btm[col + 1]);
                    p0 += h0 * W3s[col * 2 + 0] + h1 * W3s[(col + 1) * 2 + 0];
                    p1 += h0 * W3s[col * 2 + 1] + h1 * W3s[(col + 1) * 2 + 1];
                }
                p0 += __shfl_xor_sync(0xffffffffu, p0, 1);
                p1 += __shfl_xor_sync(0xffffffffu, p1, 1);
                p0 += __shfl_xor_sync(0xffffffffu, p0, 2);
                p1 += __shfl_xor_sync(0xffffffffu, p1, 2);
                if (tq == 0) {
                    atomicAdd(&pout[rowl * 2 + 0], p0);
                    atomicAdd(&pout[rowl * 2 + 1], p1);
                }
            }
        }
        __syncthreads();

        if (t < 128) out[((size_t)bt * N_ + r0) * DOUT + t] = pout[t];
        __syncthreads();
    }
}

// ---------------------------------------------------------------------------
extern "C" void kernel_launch(void* const* d_in, const int* in_sizes, int n_in,
                              void* d_out, int out_size)
{
    const float* eb   = (const float*)d_in[0];
    const float* teb  = (const float*)d_in[1];
    const float* neb  = (const float*)d_in[2];
    const float* W1   = (const float*)d_in[3];
    const float* b1   = (const float*)d_in[4];
    const float* W3   = (const float*)d_in[5];
    const float* b3   = (const float*)d_in[6];
    const float* pws  = (const float*)d_in[7];
    const float* pbs  = (const float*)d_in[8];
    const float* pwt  = (const float*)d_in[9];
    const float* pbt  = (const float*)d_in[10];
    float* out = (float*)d_out;

    const size_t smp = (size_t)(DIN * HID + HID * HID) * sizeof(float);

    cudaFuncSetAttribute((const void*)k_pre,      cudaFuncAttributeMaxDynamicSharedMemorySize, (int)smp);
    cudaFuncSetAttribute((const void*)k_spatial,  cudaFuncAttributeMaxDynamicSharedMemorySize, SP_TOT);
    cudaFuncSetAttribute((const void*)k_temporal, cudaFuncAttributeMaxDynamicSharedMemorySize, SMB_TOT);

    k_pre<<<EMB, 256, smp>>>(W1, b1, pws, pbs);
    dim3 g1(N_, 2);
    k_spatial<<<g1, 256, SP_TOT>>>(eb, neb);
    k_temporal<<<BT, 256, SMB_TOT>>>(teb, pwt, pbt, W3, b3, out);
}

// round 12
// speedup vs baseline: 4.6315x; 1.1640x over previous
#include <cuda_runtime.h>
#include <cuda_bf16.h>
#include <cstdint>

#define B_    32
#define T_    24
#define N_    512
#define BT    768
#define DIN   64
#define HID   128
#define EMB   16
#define DOUT  2
#define NEG   0.01f

// Inter-kernel scratch
__device__ __nv_bfloat16 g_hi[(size_t)BT * N_ * HID];
__device__ __nv_bfloat16 g_lo[(size_t)BT * N_ * HID];
__device__ float g_P[(size_t)EMB * DIN * HID];     // P[d] = W1 @ pool_w_spa[d]
__device__ float g_pbe[(size_t)EMB * HID];
// Materialized weights (transposed [o][i], bf16 hi/lo)
__device__ __nv_bfloat16 g_wt_hi[(size_t)BT * HID * HID];
__device__ __nv_bfloat16 g_wt_lo[(size_t)BT * HID * HID];
__device__ __nv_bfloat16 g_we_hi[(size_t)N_ * HID * DIN];
__device__ __nv_bfloat16 g_we_lo[(size_t)N_ * HID * DIN];

__device__ __forceinline__ float lrelu(float x) { return x >= 0.f ? x : NEG * x; }

__device__ __forceinline__ uint32_t smem_u32(const void* p) {
    uint32_t a;
    asm("{ .reg .u64 t; cvta.to.shared.u64 t, %1; cvt.u32.u64 %0, t; }" : "=r"(a) : "l"(p));
    return a;
}
__device__ __forceinline__ void ldsm_x4(uint32_t* r, uint32_t addr) {
    asm volatile("ldmatrix.sync.aligned.m8n8.x4.shared.b16 {%0,%1,%2,%3}, [%4];"
                 : "=r"(r[0]), "=r"(r[1]), "=r"(r[2]), "=r"(r[3]) : "r"(addr));
}
__device__ __forceinline__ void mma_bf16(float* d, const uint32_t* a, uint32_t b0, uint32_t b1) {
    asm volatile("mma.sync.aligned.m16n8k16.row.col.f32.bf16.bf16.f32 "
                 "{%0,%1,%2,%3}, {%4,%5,%6,%7}, {%8,%9}, {%0,%1,%2,%3};"
                 : "+f"(d[0]), "+f"(d[1]), "+f"(d[2]), "+f"(d[3])
                 : "r"(a[0]), "r"(a[1]), "r"(a[2]), "r"(a[3]), "r"(b0), "r"(b1));
}
__device__ __forceinline__ uint32_t pack_bf16_hi(float a, float b) {
    __nv_bfloat16 ha = __float2bfloat16(a), hb = __float2bfloat16(b);
    return (uint32_t)*(uint16_t*)&ha | ((uint32_t)*(uint16_t*)&hb << 16);
}
__device__ __forceinline__ void split_pack(float a, float b, uint32_t& hp, uint32_t& lp) {
    __nv_bfloat16 ha = __float2bfloat16(a), hb = __float2bfloat16(b);
    hp = (uint32_t)*(uint16_t*)&ha | ((uint32_t)*(uint16_t*)&hb << 16);
    lp = pack_bf16_hi(a - __bfloat162float(ha), b - __bfloat162float(hb));
}

// ---------------------------------------------------------------------------
// k_pre: g_P[d] = W1 @ pool_w_spa[d]; g_pbe[d] = b1@pool_w_spa[d] + pool_b_spa[d]
// grid (EMB, 4): y splits the 64 output rows into 16-row slices.
// ---------------------------------------------------------------------------
__global__ void __launch_bounds__(256)
k_pre(const float* __restrict__ W1, const float* __restrict__ b1,
      const float* __restrict__ pool_w, const float* __restrict__ pool_b)
{
    extern __shared__ float sp[];
    float* W1s = sp;                  // 16x128
    float* Pl  = sp + 16 * HID;       // 128x128

    const int d  = blockIdx.x;
    const int r0 = blockIdx.y * 16;
    const int t  = threadIdx.x;
    const int rg = t >> 4, cg = t & 15;

    for (int e = t; e < 16 * HID; e += 256) W1s[e] = W1[r0 * HID + e];
    for (int e = t; e < HID * HID; e += 256) Pl[e] = pool_w[(size_t)d * HID * HID + e];
    __syncthreads();

    float acc[8];
#pragma unroll
    for (int j = 0; j < 8; j++) acc[j] = 0.f;

    const float* ar = W1s + rg * HID;
    const float* wc = Pl + cg * 8;
#pragma unroll 4
    for (int k = 0; k < HID; k++) {
        float a = ar[k];
        float4 w0 = *(const float4*)(wc + k * HID);
        float4 w1 = *(const float4*)(wc + k * HID + 4);
        acc[0] += a * w0.x; acc[1] += a * w0.y; acc[2] += a * w0.z; acc[3] += a * w0.w;
        acc[4] += a * w1.x; acc[5] += a * w1.y; acc[6] += a * w1.z; acc[7] += a * w1.w;
    }
#pragma unroll
    for (int j = 0; j < 8; j++)
        g_P[(size_t)d * DIN * HID + (r0 + rg) * HID + cg * 8 + j] = acc[j];

    if (blockIdx.y == 0 && t < HID) {
        float s = pool_b[d * HID + t];
#pragma unroll 8
        for (int k = 0; k < HID; k++) s += b1[k] * Pl[k * HID + t];
        g_pbe[d * HID + t] = s;
    }
}

// ---------------------------------------------------------------------------
// k_wtem: materialize W_tem^T hi/lo for all bt.
//   g_wt[bt][o][i] = sum_d te[bt][d] * pool_w_tem[d][i][o]
// grid (12 bt-groups of 64, 16 o-slices of 8). smem: Ps[16][8][132] + te[4][16]
// ---------------------------------------------------------------------------
#define WT_PSLD 132
#define WT_SM   (16 * 8 * WT_PSLD * 4 + 256)

__global__ void __launch_bounds__(256)
k_wtem(const float* __restrict__ time_eb, const float* __restrict__ pool_w)
{
    extern __shared__ float sp[];
    float* Ps  = sp;                          // [d][orel][132]
    float* tes = sp + 16 * 8 * WT_PSLD;       // [4][16]

    const int btg0 = blockIdx.x * 64;
    const int o0   = blockIdx.y * 8;
    const int t    = threadIdx.x;

    // transpose-load pool slice: Ps[d][orel][i] = pool_w[d][i][o0+orel]
#pragma unroll
    for (int it = 0; it < 64; it++) {
        int idx = t + it * 256;               // 16384
        int d = idx >> 10, rem = idx & 1023;
        int i = rem >> 3, orel = rem & 7;
        Ps[d * (8 * WT_PSLD) + orel * WT_PSLD + i] =
            pool_w[(size_t)d * HID * HID + i * HID + o0 + orel];
    }
    __syncthreads();

    const int orel = t >> 5;
    const int i0   = (t & 31) * 4;

#pragma unroll 1
    for (int gq = 0; gq < 16; gq++) {
        const int bt0 = btg0 + gq * 4;
        if (t < 64) tes[t] = time_eb[(bt0 + (t >> 4)) * EMB + (t & 15)];
        __syncthreads();

        float acc[4][4];
#pragma unroll
        for (int b = 0; b < 4; b++)
#pragma unroll
            for (int q = 0; q < 4; q++) acc[b][q] = 0.f;

#pragma unroll
        for (int d = 0; d < EMB; d++) {
            float4 p = *(const float4*)(Ps + d * (8 * WT_PSLD) + orel * WT_PSLD + i0);
#pragma unroll
            for (int b = 0; b < 4; b++) {
                float te = tes[b * EMB + d];
                acc[b][0] += te * p.x; acc[b][1] += te * p.y;
                acc[b][2] += te * p.z; acc[b][3] += te * p.w;
            }
        }
#pragma unroll
        for (int b = 0; b < 4; b++) {
            uint2 hp, lp;
            split_pack(acc[b][0], acc[b][1], hp.x, lp.x);
            split_pack(acc[b][2], acc[b][3], hp.y, lp.y);
            size_t off = (size_t)(bt0 + b) * HID * HID + (o0 + orel) * HID + i0;
            *(uint2*)(g_wt_hi + off) = hp;
            *(uint2*)(g_wt_lo + off) = lp;
        }
        __syncthreads();
    }
}

// ---------------------------------------------------------------------------
// k_weff: materialize W_eff^T hi/lo for all n.
//   g_we[n][o][i] = sum_d ne[n][d] * g_P[d][i][o]   (i in 0..63)
// grid (8 n-groups of 64, 16 o-slices of 8). smem: Ps[16][8][68] + ne[4][16]
// ---------------------------------------------------------------------------
#define WE_PSLD 68
#define WE_SM   (16 * 8 * WE_PSLD * 4 + 256)

__global__ void __launch_bounds__(256)
k_weff(const float* __restrict__ node_eb)
{
    extern __shared__ float sp[];
    float* Ps  = sp;                          // [d][orel][68]
    float* nes = sp + 16 * 8 * WE_PSLD;

    const int ng0 = blockIdx.x * 64;
    const int o0  = blockIdx.y * 8;
    const int t   = threadIdx.x;

#pragma unroll
    for (int it = 0; it < 32; it++) {
        int idx = t + it * 256;               // 8192
        int d = idx >> 9, rem = idx & 511;
        int i = rem >> 3, orel = rem & 7;
        Ps[d * (8 * WE_PSLD) + orel * WE_PSLD + i] =
            g_P[(size_t)d * DIN * HID + i * HID + o0 + orel];
    }
    __syncthreads();

    const int orel = t >> 5;
    const int i0   = (t & 31) * 2;

#pragma unroll 1
    for (int gq = 0; gq < 16; gq++) {
        const int n0 = ng0 + gq * 4;
        if (t < 64) nes[t] = node_eb[(n0 + (t >> 4)) * EMB + (t & 15)];
        __syncthreads();

        float acc[4][2];
#pragma unroll
        for (int b = 0; b < 4; b++) { acc[b][0] = 0.f; acc[b][1] = 0.f; }

#pragma unroll
        for (int d = 0; d < EMB; d++) {
            float2 p = *(const float2*)(Ps + d * (8 * WE_PSLD) + orel * WE_PSLD + i0);
#pragma unroll
            for (int b = 0; b < 4; b++) {
                float ne = nes[b * EMB + d];
                acc[b][0] += ne * p.x; acc[b][1] += ne * p.y;
            }
        }
#pragma unroll
        for (int b = 0; b < 4; b++) {
            uint32_t hp, lp;
            split_pack(acc[b][0], acc[b][1], hp, lp);
            size_t off = (size_t)(n0 + b) * HID * DIN + (o0 + orel) * DIN + i0;
            *(uint32_t*)(g_we_hi + off) = hp;
            *(uint32_t*)(g_we_lo + off) = lp;
        }
        __syncthreads();
    }
}

// ---------------------------------------------------------------------------
// Kernel A (spatial), mma.sync bf16 hi/lo: one block per (node, bt-half).
// Weights loaded from g_we (materialized). smem layout as R11.
// ---------------------------------------------------------------------------
#define SLD     144
#define SP_BSP  0
#define SP_BHI  512
#define SP_BLO  18944
#define SP_AHI  37376
#define SP_ALO  46592
#define SP_TOT  55808

__global__ void __launch_bounds__(256)
k_spatial(const float* __restrict__ eb, const float* __restrict__ node_eb)
{
    extern __shared__ char smch[];
    const uint32_t smb = smem_u32(smch);
    float* bsp = (float*)(smch + SP_BSP);

    const int n   = blockIdx.x;
    const int t   = threadIdx.x;
    const int wid = t >> 5;
    const int l   = t & 31;

    // --- load B = W_eff^T hi/lo from g_we (128 rows x 128B) ---
#pragma unroll
    for (int i = 0; i < 4; i++) {
        int c = t + i * 256;                 // 0..1023
        int r = c >> 3, q = c & 7;
        size_t src = (size_t)n * HID * DIN + r * DIN + q * 8;
        *(uint4*)(smch + SP_BHI + r * SLD + q * 16) = *(const uint4*)(g_we_hi + src);
        *(uint4*)(smch + SP_BLO + r * SLD + q * 16) = *(const uint4*)(g_we_lo + src);
    }
    if (t < HID) {
        float s = 0.f;
#pragma unroll
        for (int d = 0; d < EMB; d++) s += node_eb[n * EMB + d] * g_pbe[d * HID + t];
        bsp[t] = s;
    }

    const int mw = wid & 1, nw = wid >> 1;
    const int m0w = mw * 32, n0w = nw * 32;
    const int g  = l >> 2, tq = l & 3;
    const uint32_t aoff = (uint32_t)(((l & 7) + ((l >> 3) & 1) * 8) * SLD + ((l >> 4) & 1) * 16);
    const uint32_t boff = (uint32_t)(((l & 7) + ((l >> 4) & 1) * 8) * SLD + ((l >> 3) & 1) * 16);
    const uint32_t APASS[3] = {SP_AHI, SP_ALO, SP_AHI};
    const uint32_t BPASS[3] = {SP_BHI, SP_BHI, SP_BLO};

    __syncthreads();

    const int c_base = blockIdx.y * (BT / 2);
#pragma unroll 1
    for (int tt = 0; tt < BT / 2; tt += 64) {
        const int c0 = c_base + tt;

        // --- load x tile [64 x 64] fp32, split hi/lo into smem ---
#pragma unroll
        for (int i = 0; i < 4; i++) {
            int chunk = t + i * 256;
            int r = chunk >> 4, q = chunk & 15;
            float4 v = *(const float4*)(eb + ((size_t)(c0 + r) * N_ + n) * DIN + q * 4);
            uint2 uh, ul;
            split_pack(v.x, v.y, uh.x, ul.x);
            split_pack(v.z, v.w, uh.y, ul.y);
            *(uint2*)(smch + SP_AHI + r * SLD + q * 8) = uh;
            *(uint2*)(smch + SP_ALO + r * SLD + q * 8) = ul;
        }
        __syncthreads();

        float acc[2][4][4];
#pragma unroll
        for (int mi = 0; mi < 2; mi++)
#pragma unroll
            for (int nj = 0; nj < 4; nj++)
#pragma unroll
                for (int q = 0; q < 4; q++) acc[mi][nj][q] = 0.f;

#pragma unroll 1
        for (int p = 0; p < 3; p++) {
            const uint32_t Ab = smb + APASS[p] + (uint32_t)m0w * SLD + aoff;
            const uint32_t Bb = smb + BPASS[p] + (uint32_t)n0w * SLD + boff;
#pragma unroll
            for (int kc = 0; kc < 4; kc++) {
                uint32_t a0[4], a1[4], bA[4], bB[4];
                ldsm_x4(a0, Ab + kc * 32);
                ldsm_x4(a1, Ab + 16 * SLD + kc * 32);
                ldsm_x4(bA, Bb + kc * 32);
                ldsm_x4(bB, Bb + 16 * SLD + kc * 32);
                mma_bf16(acc[0][0], a0, bA[0], bA[1]);
                mma_bf16(acc[0][1], a0, bA[2], bA[3]);
                mma_bf16(acc[0][2], a0, bB[0], bB[1]);
                mma_bf16(acc[0][3], a0, bB[2], bB[3]);
                mma_bf16(acc[1][0], a1, bA[0], bA[1]);
                mma_bf16(acc[1][1], a1, bA[2], bA[3]);
                mma_bf16(acc[1][2], a1, bB[0], bB[1]);
                mma_bf16(acc[1][3], a1, bB[2], bB[3]);
            }
        }

#pragma unroll
        for (int mi = 0; mi < 2; mi++) {
#pragma unroll
            for (int rh = 0; rh < 2; rh++) {
                const int row = m0w + 16 * mi + 8 * rh + g;
                const size_t base = ((size_t)(c0 + row) * N_ + n) * HID;
#pragma unroll
                for (int nj = 0; nj < 4; nj++) {
                    const int col = n0w + 8 * nj + 2 * tq;
                    float h0 = lrelu(acc[mi][nj][rh * 2 + 0] + bsp[col]);
                    float h1 = lrelu(acc[mi][nj][rh * 2 + 1] + bsp[col + 1]);
                    uint32_t hp, lp;
                    split_pack(h0, h1, hp, lp);
                    *(uint32_t*)(g_hi + base + col) = hp;
                    *(uint32_t*)(g_lo + base + col) = lp;
                }
            }
        }
        __syncthreads();
    }
}

// ---------------------------------------------------------------------------
// Kernel B (temporal): weights loaded from g_wt (materialized). As R11 else.
// ---------------------------------------------------------------------------
#define TLD   272
#define SMB_BTM  0
#define SMB_W3   512
#define SMB_POUT 1536
#define SMB_BHI  2048
#define SMB_BLO  36864
#define SMB_AHI  71680
#define SMB_ALO  89088
#define SMB_TOT  106496

__global__ void __launch_bounds__(256, 2)
k_temporal(const float* __restrict__ time_eb,
           const float* __restrict__ pool_b,
           const float* __restrict__ W3,
           const float* __restrict__ b3,
           float* __restrict__ out)
{
    extern __shared__ char smch[];
    const uint32_t smb = smem_u32(smch);
    float* btm  = (float*)(smch + SMB_BTM);
    float* W3s  = (float*)(smch + SMB_W3);
    float* pout = (float*)(smch + SMB_POUT);

    const int bt  = blockIdx.x;
    const int t   = threadIdx.x;
    const int wid = t >> 5;
    const int l   = t & 31;

    if (t < HID) {
        float s = 0.f;
#pragma unroll
        for (int d = 0; d < EMB; d++) s += time_eb[bt * EMB + d] * pool_b[d * HID + t];
        btm[t] = s;
    }
    if (t < HID * DOUT) W3s[t] = W3[t];

    // --- load B = W_tem^T hi/lo from g_wt (128 rows x 256B) ---
#pragma unroll
    for (int i = 0; i < 8; i++) {
        int c = t + i * 256;                 // 0..2047
        int r = c >> 4, q = c & 15;
        size_t src = (size_t)bt * HID * HID + r * HID + q * 8;
        *(uint4*)(smch + SMB_BHI + r * TLD + q * 16) = *(const uint4*)(g_wt_hi + src);
        *(uint4*)(smch + SMB_BLO + r * TLD + q * 16) = *(const uint4*)(g_wt_lo + src);
    }

    const int mw = wid & 1, nw = wid >> 1;
    const int m0w = mw * 32, n0w = nw * 32;
    const int g  = l >> 2, tq = l & 3;
    const uint32_t aoff = (uint32_t)(((l & 7) + ((l >> 3) & 1) * 8) * TLD + ((l >> 4) & 1) * 16);
    const uint32_t boff = (uint32_t)(((l & 7) + ((l >> 4) & 1) * 8) * TLD + ((l >> 3) & 1) * 16);
    const uint32_t APASS[3] = {SMB_AHI, SMB_ALO, SMB_AHI};
    const uint32_t BPASS[3] = {SMB_BHI, SMB_BHI, SMB_BLO};
    const float b30 = __ldg(b3), b31 = __ldg(b3 + 1);

    __syncthreads();

#pragma unroll 1
    for (int tile = 0; tile < 8; tile++) {
        const int r0 = tile * 64;

#pragma unroll
        for (int i = 0; i < 4; i++) {
            int chunk = t + i * 256;
            int r = chunk >> 4, k16 = chunk & 15;
            size_t src = ((size_t)bt * N_ + r0 + r) * HID + k16 * 8;
            *(uint4*)(smch + SMB_AHI + r * TLD + k16 * 16) = *(const uint4*)(g_hi + src);
            *(uint4*)(smch + SMB_ALO + r * TLD + k16 * 16) = *(const uint4*)(g_lo + src);
        }
        if (t < 128) pout[t] = (t & 1) ? b31 : b30;
        __syncthreads();

        float acc[2][4][4];
#pragma unroll
        for (int mi = 0; mi < 2; mi++)
#pragma unroll
            for (int nj = 0; nj < 4; nj++)
#pragma unroll
                for (int q = 0; q < 4; q++) acc[mi][nj][q] = 0.f;

#pragma unroll 1
        for (int p = 0; p < 3; p++) {
            const uint32_t Ab = smb + APASS[p] + (uint32_t)m0w * TLD + aoff;
            const uint32_t Bb = smb + BPASS[p] + (uint32_t)n0w * TLD + boff;
#pragma unroll 4
            for (int kc = 0; kc < 8; kc++) {
                uint32_t a0[4], a1[4], bA[4], bB[4];
                ldsm_x4(a0, Ab + kc * 32);
                ldsm_x4(a1, Ab + 16 * TLD + kc * 32);
                ldsm_x4(bA, Bb + kc * 32);
                ldsm_x4(bB, Bb + 16 * TLD + kc * 32);
                mma_bf16(acc[0][0], a0, bA[0], bA[1]);
                mma_bf16(acc[0][1], a0, bA[2], bA[3]);
                mma_bf16(acc[0][2], a0, bB[0], bB[1]);
                mma_bf16(acc[0][3], a0, bB[2], bB[3]);
                mma_bf16(acc[1][0], a1, bA[0], bA[1]);
                mma_bf16(acc[1][1], a1, bA[2], bA[3]);
                mma_bf16(acc[1][2], a1, bB[0], bB[1]);
                mma_bf16(acc[1][3], a1, bB[2], bB[3]);
            }
        }

#pragma unroll
        for (int mi = 0; mi < 2; mi++) {
#pragma unroll
            for (int rh = 0; rh < 2; rh++) {
                int rowl = m0w + 16 * mi + 8 * rh + g;
                float p0 = 0.f, p1 = 0.f;
#pragma unroll
                for (int nj = 0; nj < 4; nj++) {
                    int col = n0w + 8 * nj + 2 * tq;
                    float h0 = lrelu(acc[mi][nj][rh * 2 + 0] + btm[col]);
                    float h1 = lrelu(acc[mi][nj][rh * 2 + 1] + btm[col + 1]);
                    p0 += h0 * W3s[col * 2 + 0] + h1 * W3s[(col + 1) * 2 + 0];
                    p1 += h0 * W3s[col * 2 + 1] + h1 * W3s[(col + 1) * 2 + 1];
                }
                p0 += __shfl_xor_sync(0xffffffffu, p0, 1);
                p1 += __shfl_xor_sync(0xffffffffu, p1, 1);
                p0 += __shfl_xor_sync(0xffffffffu, p0, 2);
                p1 += __shfl_xor_sync(0xffffffffu, p1, 2);
                if (tq == 0) {
                    atomicAdd(&pout[rowl * 2 + 0], p0);
                    atomicAdd(&pout[rowl * 2 + 1], p1);
                }
            }
        }
        __syncthreads();

        if (t < 128) out[((size_t)bt * N_ + r0) * DOUT + t] = pout[t];
        __syncthreads();
    }
}

// ---------------------------------------------------------------------------
extern "C" void kernel_launch(void* const* d_in, const int* in_sizes, int n_in,
                              void* d_out, int out_size)
{
    const float* eb   = (const float*)d_in[0];
    const float* teb  = (const float*)d_in[1];
    const float* neb  = (const float*)d_in[2];
    const float* W1   = (const float*)d_in[3];
    const float* b1   = (const float*)d_in[4];
    const float* W3   = (const float*)d_in[5];
    const float* b3   = (const float*)d_in[6];
    const float* pws  = (const float*)d_in[7];
    const float* pbs  = (const float*)d_in[8];
    const float* pwt  = (const float*)d_in[9];
    const float* pbt  = (const float*)d_in[10];
    float* out = (float*)d_out;

    const int smp = (16 * HID + HID * HID) * sizeof(float);

    cudaFuncSetAttribute((const void*)k_pre,      cudaFuncAttributeMaxDynamicSharedMemorySize, smp);
    cudaFuncSetAttribute((const void*)k_wtem,     cudaFuncAttributeMaxDynamicSharedMemorySize, WT_SM);
    cudaFuncSetAttribute((const void*)k_weff,     cudaFuncAttributeMaxDynamicSharedMemorySize, WE_SM);
    cudaFuncSetAttribute((const void*)k_spatial,  cudaFuncAttributeMaxDynamicSharedMemorySize, SP_TOT);
    cudaFuncSetAttribute((const void*)k_temporal, cudaFuncAttributeMaxDynamicSharedMemorySize, SMB_TOT);

    k_pre<<<dim3(EMB, 4), 256, smp>>>(W1, b1, pws, pbs);
    k_wtem<<<dim3(12, 16), 256, WT_SM>>>(teb, pwt);
    k_weff<<<dim3(8, 16), 256, WE_SM>>>(neb);
    k_spatial<<<dim3(N_, 2), 256, SP_TOT>>>(eb, neb);
    k_temporal<<<BT, 256, SMB_TOT>>>(teb, pbt, W3, b3, out);
}

// round 13
// speedup vs baseline: 5.0107x; 1.0819x over previous
#include <cuda_runtime.h>
#include <cuda_bf16.h>
#include <cstdint>

#define B_    32
#define T_    24
#define N_    512
#define BT    768
#define DIN   64
#define HID   128
#define EMB   16
#define DOUT  2
#define NEG   0.01f

// Inter-kernel scratch
__device__ __nv_bfloat16 g_hi[(size_t)BT * N_ * HID];
__device__ __nv_bfloat16 g_lo[(size_t)BT * N_ * HID];
__device__ float g_P[(size_t)EMB * DIN * HID];     // P[d] = W1 @ pool_w_spa[d]
__device__ float g_pbe[(size_t)EMB * HID];
// Materialized weights (transposed [o][i], bf16 hi/lo)
__device__ __nv_bfloat16 g_wt_hi[(size_t)BT * HID * HID];
__device__ __nv_bfloat16 g_wt_lo[(size_t)BT * HID * HID];
__device__ __nv_bfloat16 g_we_hi[(size_t)N_ * HID * DIN];
__device__ __nv_bfloat16 g_we_lo[(size_t)N_ * HID * DIN];

__device__ __forceinline__ float lrelu(float x) { return x >= 0.f ? x : NEG * x; }

__device__ __forceinline__ uint32_t smem_u32(const void* p) {
    uint32_t a;
    asm("{ .reg .u64 t; cvta.to.shared.u64 t, %1; cvt.u32.u64 %0, t; }" : "=r"(a) : "l"(p));
    return a;
}
__device__ __forceinline__ void ldsm_x4(uint32_t* r, uint32_t addr) {
    asm volatile("ldmatrix.sync.aligned.m8n8.x4.shared.b16 {%0,%1,%2,%3}, [%4];"
                 : "=r"(r[0]), "=r"(r[1]), "=r"(r[2]), "=r"(r[3]) : "r"(addr));
}
__device__ __forceinline__ void mma_bf16(float* d, const uint32_t* a, uint32_t b0, uint32_t b1) {
    asm volatile("mma.sync.aligned.m16n8k16.row.col.f32.bf16.bf16.f32 "
                 "{%0,%1,%2,%3}, {%4,%5,%6,%7}, {%8,%9}, {%0,%1,%2,%3};"
                 : "+f"(d[0]), "+f"(d[1]), "+f"(d[2]), "+f"(d[3])
                 : "r"(a[0]), "r"(a[1]), "r"(a[2]), "r"(a[3]), "r"(b0), "r"(b1));
}
__device__ __forceinline__ uint32_t pack_bf16_hi(float a, float b) {
    __nv_bfloat16 ha = __float2bfloat16(a), hb = __float2bfloat16(b);
    return (uint32_t)*(uint16_t*)&ha | ((uint32_t)*(uint16_t*)&hb << 16);
}
__device__ __forceinline__ void split_pack(float a, float b, uint32_t& hp, uint32_t& lp) {
    __nv_bfloat16 ha = __float2bfloat16(a), hb = __float2bfloat16(b);
    hp = (uint32_t)*(uint16_t*)&ha | ((uint32_t)*(uint16_t*)&hb << 16);
    lp = pack_bf16_hi(a - __bfloat162float(ha), b - __bfloat162float(hb));
}

// 24 fused MMAs for the 3-term hi/lo product on one kc chunk
#define MMA_FUSED_24(acc, ah0, ah1, al0, al1, bhA, bhB, blA, blB) do {     \
    mma_bf16(acc[0][0], ah0, bhA[0], bhA[1]);                              \
    mma_bf16(acc[0][1], ah0, bhA[2], bhA[3]);                              \
    mma_bf16(acc[0][2], ah0, bhB[0], bhB[1]);                              \
    mma_bf16(acc[0][3], ah0, bhB[2], bhB[3]);                              \
    mma_bf16(acc[1][0], ah1, bhA[0], bhA[1]);                              \
    mma_bf16(acc[1][1], ah1, bhA[2], bhA[3]);                              \
    mma_bf16(acc[1][2], ah1, bhB[0], bhB[1]);                              \
    mma_bf16(acc[1][3], ah1, bhB[2], bhB[3]);                              \
    mma_bf16(acc[0][0], al0, bhA[0], bhA[1]);                              \
    mma_bf16(acc[0][1], al0, bhA[2], bhA[3]);                              \
    mma_bf16(acc[0][2], al0, bhB[0], bhB[1]);                              \
    mma_bf16(acc[0][3], al0, bhB[2], bhB[3]);                              \
    mma_bf16(acc[1][0], al1, bhA[0], bhA[1]);                              \
    mma_bf16(acc[1][1], al1, bhA[2], bhA[3]);                              \
    mma_bf16(acc[1][2], al1, bhB[0], bhB[1]);                              \
    mma_bf16(acc[1][3], al1, bhB[2], bhB[3]);                              \
    mma_bf16(acc[0][0], ah0, blA[0], blA[1]);                              \
    mma_bf16(acc[0][1], ah0, blA[2], blA[3]);                              \
    mma_bf16(acc[0][2], ah0, blB[0], blB[1]);                              \
    mma_bf16(acc[0][3], ah0, blB[2], blB[3]);                              \
    mma_bf16(acc[1][0], ah1, blA[0], blA[1]);                              \
    mma_bf16(acc[1][1], ah1, blA[2], blA[3]);                              \
    mma_bf16(acc[1][2], ah1, blB[0], blB[1]);                              \
    mma_bf16(acc[1][3], ah1, blB[2], blB[3]);                              \
} while (0)

// ---------------------------------------------------------------------------
// k_pre: g_P[d] = W1 @ pool_w_spa[d]; g_pbe[d] = b1@pool_w_spa[d] + pool_b_spa[d]
// ---------------------------------------------------------------------------
__global__ void __launch_bounds__(256)
k_pre(const float* __restrict__ W1, const float* __restrict__ b1,
      const float* __restrict__ pool_w, const float* __restrict__ pool_b)
{
    extern __shared__ float sp[];
    float* W1s = sp;                  // 16x128
    float* Pl  = sp + 16 * HID;       // 128x128

    const int d  = blockIdx.x;
    const int r0 = blockIdx.y * 16;
    const int t  = threadIdx.x;
    const int rg = t >> 4, cg = t & 15;

    for (int e = t; e < 16 * HID; e += 256) W1s[e] = W1[r0 * HID + e];
    for (int e = t; e < HID * HID; e += 256) Pl[e] = pool_w[(size_t)d * HID * HID + e];
    __syncthreads();

    float acc[8];
#pragma unroll
    for (int j = 0; j < 8; j++) acc[j] = 0.f;

    const float* ar = W1s + rg * HID;
    const float* wc = Pl + cg * 8;
#pragma unroll 4
    for (int k = 0; k < HID; k++) {
        float a = ar[k];
        float4 w0 = *(const float4*)(wc + k * HID);
        float4 w1 = *(const float4*)(wc + k * HID + 4);
        acc[0] += a * w0.x; acc[1] += a * w0.y; acc[2] += a * w0.z; acc[3] += a * w0.w;
        acc[4] += a * w1.x; acc[5] += a * w1.y; acc[6] += a * w1.z; acc[7] += a * w1.w;
    }
#pragma unroll
    for (int j = 0; j < 8; j++)
        g_P[(size_t)d * DIN * HID + (r0 + rg) * HID + cg * 8 + j] = acc[j];

    if (blockIdx.y == 0 && t < HID) {
        float s = pool_b[d * HID + t];
#pragma unroll 8
        for (int k = 0; k < HID; k++) s += b1[k] * Pl[k * HID + t];
        g_pbe[d * HID + t] = s;
    }
}

// ---------------------------------------------------------------------------
// k_wtem: materialize W_tem^T hi/lo for all bt.
// ---------------------------------------------------------------------------
#define WT_PSLD 132
#define WT_SM   (16 * 8 * WT_PSLD * 4 + 256)

__global__ void __launch_bounds__(256)
k_wtem(const float* __restrict__ time_eb, const float* __restrict__ pool_w)
{
    extern __shared__ float sp[];
    float* Ps  = sp;                          // [d][orel][132]
    float* tes = sp + 16 * 8 * WT_PSLD;       // [4][16]

    const int btg0 = blockIdx.x * 64;
    const int o0   = blockIdx.y * 8;
    const int t    = threadIdx.x;

#pragma unroll
    for (int it = 0; it < 64; it++) {
        int idx = t + it * 256;
        int d = idx >> 10, rem = idx & 1023;
        int i = rem >> 3, orel = rem & 7;
        Ps[d * (8 * WT_PSLD) + orel * WT_PSLD + i] =
            pool_w[(size_t)d * HID * HID + i * HID + o0 + orel];
    }
    __syncthreads();

    const int orel = t >> 5;
    const int i0   = (t & 31) * 4;

#pragma unroll 1
    for (int gq = 0; gq < 16; gq++) {
        const int bt0 = btg0 + gq * 4;
        if (t < 64) tes[t] = time_eb[(bt0 + (t >> 4)) * EMB + (t & 15)];
        __syncthreads();

        float acc[4][4];
#pragma unroll
        for (int b = 0; b < 4; b++)
#pragma unroll
            for (int q = 0; q < 4; q++) acc[b][q] = 0.f;

#pragma unroll
        for (int d = 0; d < EMB; d++) {
            float4 p = *(const float4*)(Ps + d * (8 * WT_PSLD) + orel * WT_PSLD + i0);
#pragma unroll
            for (int b = 0; b < 4; b++) {
                float te = tes[b * EMB + d];
                acc[b][0] += te * p.x; acc[b][1] += te * p.y;
                acc[b][2] += te * p.z; acc[b][3] += te * p.w;
            }
        }
#pragma unroll
        for (int b = 0; b < 4; b++) {
            uint2 hp, lp;
            split_pack(acc[b][0], acc[b][1], hp.x, lp.x);
            split_pack(acc[b][2], acc[b][3], hp.y, lp.y);
            size_t off = (size_t)(bt0 + b) * HID * HID + (o0 + orel) * HID + i0;
            *(uint2*)(g_wt_hi + off) = hp;
            *(uint2*)(g_wt_lo + off) = lp;
        }
        __syncthreads();
    }
}

// ---------------------------------------------------------------------------
// k_weff: materialize W_eff^T hi/lo for all n.
// ---------------------------------------------------------------------------
#define WE_PSLD 68
#define WE_SM   (16 * 8 * WE_PSLD * 4 + 256)

__global__ void __launch_bounds__(256)
k_weff(const float* __restrict__ node_eb)
{
    extern __shared__ float sp[];
    float* Ps  = sp;                          // [d][orel][68]
    float* nes = sp + 16 * 8 * WE_PSLD;

    const int ng0 = blockIdx.x * 64;
    const int o0  = blockIdx.y * 8;
    const int t   = threadIdx.x;

#pragma unroll
    for (int it = 0; it < 32; it++) {
        int idx = t + it * 256;
        int d = idx >> 9, rem = idx & 511;
        int i = rem >> 3, orel = rem & 7;
        Ps[d * (8 * WE_PSLD) + orel * WE_PSLD + i] =
            g_P[(size_t)d * DIN * HID + i * HID + o0 + orel];
    }
    __syncthreads();

    const int orel = t >> 5;
    const int i0   = (t & 31) * 2;

#pragma unroll 1
    for (int gq = 0; gq < 16; gq++) {
        const int n0 = ng0 + gq * 4;
        if (t < 64) nes[t] = node_eb[(n0 + (t >> 4)) * EMB + (t & 15)];
        __syncthreads();

        float acc[4][2];
#pragma unroll
        for (int b = 0; b < 4; b++) { acc[b][0] = 0.f; acc[b][1] = 0.f; }

#pragma unroll
        for (int d = 0; d < EMB; d++) {
            float2 p = *(const float2*)(Ps + d * (8 * WE_PSLD) + orel * WE_PSLD + i0);
#pragma unroll
            for (int b = 0; b < 4; b++) {
                float ne = nes[b * EMB + d];
                acc[b][0] += ne * p.x; acc[b][1] += ne * p.y;
            }
        }
#pragma unroll
        for (int b = 0; b < 4; b++) {
            uint32_t hp, lp;
            split_pack(acc[b][0], acc[b][1], hp, lp);
            size_t off = (size_t)(n0 + b) * HID * DIN + (o0 + orel) * DIN + i0;
            *(uint32_t*)(g_we_hi + off) = hp;
            *(uint32_t*)(g_we_lo + off) = lp;
        }
        __syncthreads();
    }
}

// ---------------------------------------------------------------------------
// Kernel A (spatial): fused single-pass hi/lo (8 LDSM -> 24 MMA per kc).
// ---------------------------------------------------------------------------
#define SLD     144
#define SP_BSP  0
#define SP_BHI  512
#define SP_BLO  18944
#define SP_AHI  37376
#define SP_ALO  46592
#define SP_TOT  55808

__global__ void __launch_bounds__(256, 2)
k_spatial(const float* __restrict__ eb, const float* __restrict__ node_eb)
{
    extern __shared__ char smch[];
    const uint32_t smb = smem_u32(smch);
    float* bsp = (float*)(smch + SP_BSP);

    const int n   = blockIdx.x;
    const int t   = threadIdx.x;
    const int wid = t >> 5;
    const int l   = t & 31;

#pragma unroll
    for (int i = 0; i < 4; i++) {
        int c = t + i * 256;
        int r = c >> 3, q = c & 7;
        size_t src = (size_t)n * HID * DIN + r * DIN + q * 8;
        *(uint4*)(smch + SP_BHI + r * SLD + q * 16) = *(const uint4*)(g_we_hi + src);
        *(uint4*)(smch + SP_BLO + r * SLD + q * 16) = *(const uint4*)(g_we_lo + src);
    }
    if (t < HID) {
        float s = 0.f;
#pragma unroll
        for (int d = 0; d < EMB; d++) s += node_eb[n * EMB + d] * g_pbe[d * HID + t];
        bsp[t] = s;
    }

    const int mw = wid & 1, nw = wid >> 1;
    const int m0w = mw * 32, n0w = nw * 32;
    const int g  = l >> 2, tq = l & 3;
    const uint32_t aoff = (uint32_t)(((l & 7) + ((l >> 3) & 1) * 8) * SLD + ((l >> 4) & 1) * 16);
    const uint32_t boff = (uint32_t)(((l & 7) + ((l >> 4) & 1) * 8) * SLD + ((l >> 3) & 1) * 16);
    const uint32_t AbHi = smb + SP_AHI + (uint32_t)m0w * SLD + aoff;
    const uint32_t AbLo = smb + SP_ALO + (uint32_t)m0w * SLD + aoff;
    const uint32_t BbHi = smb + SP_BHI + (uint32_t)n0w * SLD + boff;
    const uint32_t BbLo = smb + SP_BLO + (uint32_t)n0w * SLD + boff;

    __syncthreads();

    const int c_base = blockIdx.y * (BT / 2);
#pragma unroll 1
    for (int tt = 0; tt < BT / 2; tt += 64) {
        const int c0 = c_base + tt;

#pragma unroll
        for (int i = 0; i < 4; i++) {
            int chunk = t + i * 256;
            int r = chunk >> 4, q = chunk & 15;
            float4 v = *(const float4*)(eb + ((size_t)(c0 + r) * N_ + n) * DIN + q * 4);
            uint2 uh, ul;
            split_pack(v.x, v.y, uh.x, ul.x);
            split_pack(v.z, v.w, uh.y, ul.y);
            *(uint2*)(smch + SP_AHI + r * SLD + q * 8) = uh;
            *(uint2*)(smch + SP_ALO + r * SLD + q * 8) = ul;
        }
        __syncthreads();

        float acc[2][4][4];
#pragma unroll
        for (int mi = 0; mi < 2; mi++)
#pragma unroll
            for (int nj = 0; nj < 4; nj++)
#pragma unroll
                for (int q = 0; q < 4; q++) acc[mi][nj][q] = 0.f;

#pragma unroll
        for (int kc = 0; kc < 4; kc++) {
            uint32_t ah0[4], ah1[4], al0[4], al1[4], bhA[4], bhB[4], blA[4], blB[4];
            ldsm_x4(ah0, AbHi + kc * 32);
            ldsm_x4(ah1, AbHi + 16 * SLD + kc * 32);
            ldsm_x4(al0, AbLo + kc * 32);
            ldsm_x4(al1, AbLo + 16 * SLD + kc * 32);
            ldsm_x4(bhA, BbHi + kc * 32);
            ldsm_x4(bhB, BbHi + 16 * SLD + kc * 32);
            ldsm_x4(blA, BbLo + kc * 32);
            ldsm_x4(blB, BbLo + 16 * SLD + kc * 32);
            MMA_FUSED_24(acc, ah0, ah1, al0, al1, bhA, bhB, blA, blB);
        }

#pragma unroll
        for (int mi = 0; mi < 2; mi++) {
#pragma unroll
            for (int rh = 0; rh < 2; rh++) {
                const int row = m0w + 16 * mi + 8 * rh + g;
                const size_t base = ((size_t)(c0 + row) * N_ + n) * HID;
#pragma unroll
                for (int nj = 0; nj < 4; nj++) {
                    const int col = n0w + 8 * nj + 2 * tq;
                    float h0 = lrelu(acc[mi][nj][rh * 2 + 0] + bsp[col]);
                    float h1 = lrelu(acc[mi][nj][rh * 2 + 1] + bsp[col + 1]);
                    uint32_t hp, lp;
                    split_pack(h0, h1, hp, lp);
                    *(uint32_t*)(g_hi + base + col) = hp;
                    *(uint32_t*)(g_lo + base + col) = lp;
                }
            }
        }
        __syncthreads();
    }
}

// ---------------------------------------------------------------------------
// Kernel B (temporal): fused single-pass hi/lo; grid (BT, 2), 4 tiles each.
// ---------------------------------------------------------------------------
#define TLD   272
#define SMB_BTM  0
#define SMB_W3   512
#define SMB_POUT 1536
#define SMB_BHI  2048
#define SMB_BLO  36864
#define SMB_AHI  71680
#define SMB_ALO  89088
#define SMB_TOT  106496

__global__ void __launch_bounds__(256, 2)
k_temporal(const float* __restrict__ time_eb,
           const float* __restrict__ pool_b,
           const float* __restrict__ W3,
           const float* __restrict__ b3,
           float* __restrict__ out)
{
    extern __shared__ char smch[];
    const uint32_t smb = smem_u32(smch);
    float* btm  = (float*)(smch + SMB_BTM);
    float* W3s  = (float*)(smch + SMB_W3);
    float* pout = (float*)(smch + SMB_POUT);

    const int bt  = blockIdx.x;
    const int t   = threadIdx.x;
    const int wid = t >> 5;
    const int l   = t & 31;

    if (t < HID) {
        float s = 0.f;
#pragma unroll
        for (int d = 0; d < EMB; d++) s += time_eb[bt * EMB + d] * pool_b[d * HID + t];
        btm[t] = s;
    }
    if (t < HID * DOUT) W3s[t] = W3[t];

#pragma unroll
    for (int i = 0; i < 8; i++) {
        int c = t + i * 256;
        int r = c >> 4, q = c & 15;
        size_t src = (size_t)bt * HID * HID + r * HID + q * 8;
        *(uint4*)(smch + SMB_BHI + r * TLD + q * 16) = *(const uint4*)(g_wt_hi + src);
        *(uint4*)(smch + SMB_BLO + r * TLD + q * 16) = *(const uint4*)(g_wt_lo + src);
    }

    const int mw = wid & 1, nw = wid >> 1;
    const int m0w = mw * 32, n0w = nw * 32;
    const int g  = l >> 2, tq = l & 3;
    const uint32_t aoff = (uint32_t)(((l & 7) + ((l >> 3) & 1) * 8) * TLD + ((l >> 4) & 1) * 16);
    const uint32_t boff = (uint32_t)(((l & 7) + ((l >> 4) & 1) * 8) * TLD + ((l >> 3) & 1) * 16);
    const uint32_t AbHi = smb + SMB_AHI + (uint32_t)m0w * TLD + aoff;
    const uint32_t AbLo = smb + SMB_ALO + (uint32_t)m0w * TLD + aoff;
    const uint32_t BbHi = smb + SMB_BHI + (uint32_t)n0w * TLD + boff;
    const uint32_t BbLo = smb + SMB_BLO + (uint32_t)n0w * TLD + boff;
    const float b30 = __ldg(b3), b31 = __ldg(b3 + 1);

    __syncthreads();

    const int n_base = blockIdx.y * (N_ / 2);
#pragma unroll 1
    for (int tile = 0; tile < 4; tile++) {
        const int r0 = n_base + tile * 64;

#pragma unroll
        for (int i = 0; i < 4; i++) {
            int chunk = t + i * 256;
            int r = chunk >> 4, k16 = chunk & 15;
            size_t src = ((size_t)bt * N_ + r0 + r) * HID + k16 * 8;
            *(uint4*)(smch + SMB_AHI + r * TLD + k16 * 16) = *(const uint4*)(g_hi + src);
            *(uint4*)(smch + SMB_ALO + r * TLD + k16 * 16) = *(const uint4*)(g_lo + src);
        }
        if (t < 128) pout[t] = (t & 1) ? b31 : b30;
        __syncthreads();

        float acc[2][4][4];
#pragma unroll
        for (int mi = 0; mi < 2; mi++)
#pragma unroll
            for (int nj = 0; nj < 4; nj++)
#pragma unroll
                for (int q = 0; q < 4; q++) acc[mi][nj][q] = 0.f;

#pragma unroll 2
        for (int kc = 0; kc < 8; kc++) {
            uint32_t ah0[4], ah1[4], al0[4], al1[4], bhA[4], bhB[4], blA[4], blB[4];
            ldsm_x4(ah0, AbHi + kc * 32);
            ldsm_x4(ah1, AbHi + 16 * TLD + kc * 32);
            ldsm_x4(al0, AbLo + kc * 32);
            ldsm_x4(al1, AbLo + 16 * TLD + kc * 32);
            ldsm_x4(bhA, BbHi + kc * 32);
            ldsm_x4(bhB, BbHi + 16 * TLD + kc * 32);
            ldsm_x4(blA, BbLo + kc * 32);
            ldsm_x4(blB, BbLo + 16 * TLD + kc * 32);
            MMA_FUSED_24(acc, ah0, ah1, al0, al1, bhA, bhB, blA, blB);
        }

#pragma unroll
        for (int mi = 0; mi < 2; mi++) {
#pragma unroll
            for (int rh = 0; rh < 2; rh++) {
                int rowl = m0w + 16 * mi + 8 * rh + g;
                float p0 = 0.f, p1 = 0.f;
#pragma unroll
                for (int nj = 0; nj < 4; nj++) {
                    int col = n0w + 8 * nj + 2 * tq;
                    float h0 = lrelu(acc[mi][nj][rh * 2 + 0] + btm[col]);
                    float h1 = lrelu(acc[mi][nj][rh * 2 + 1] + btm[col + 1]);
                    p0 += h0 * W3s[col * 2 + 0] + h1 * W3s[(col + 1) * 2 + 0];
                    p1 += h0 * W3s[col * 2 + 1] + h1 * W3s[(col + 1) * 2 + 1];
                }
                p0 += __shfl_xor_sync(0xffffffffu, p0, 1);
                p1 += __shfl_xor_sync(0xffffffffu, p1, 1);
                p0 += __shfl_xor_sync(0xffffffffu, p0, 2);
                p1 += __shfl_xor_sync(0xffffffffu, p1, 2);
                if (tq == 0) {
                    atomicAdd(&pout[rowl * 2 + 0], p0);
                    atomicAdd(&pout[rowl * 2 + 1], p1);
                }
            }
        }
        __syncthreads();

        if (t < 128) out[((size_t)bt * N_ + r0) * DOUT + t] = pout[t];
        __syncthreads();
    }
}

// ---------------------------------------------------------------------------
extern "C" void kernel_launch(void* const* d_in, const int* in_sizes, int n_in,
                              void* d_out, int out_size)
{
    const float* eb   = (const float*)d_in[0];
    const float* teb  = (const float*)d_in[1];
    const float* neb  = (const float*)d_in[2];
    const float* W1   = (const float*)d_in[3];
    const float* b1   = (const float*)d_in[4];
    const float* W3   = (const float*)d_in[5];
    const float* b3   = (const float*)d_in[6];
    const float* pws  = (const float*)d_in[7];
    const float* pbs  = (const float*)d_in[8];
    const float* pwt  = (const float*)d_in[9];
    const float* pbt  = (const float*)d_in[10];
    float* out = (float*)d_out;

    const int smp = (16 * HID + HID * HID) * sizeof(float);

    cudaFuncSetAttribute((const void*)k_pre,      cudaFuncAttributeMaxDynamicSharedMemorySize, smp);
    cudaFuncSetAttribute((const void*)k_wtem,     cudaFuncAttributeMaxDynamicSharedMemorySize, WT_SM);
    cudaFuncSetAttribute((const void*)k_weff,     cudaFuncAttributeMaxDynamicSharedMemorySize, WE_SM);
    cudaFuncSetAttribute((const void*)k_spatial,  cudaFuncAttributeMaxDynamicSharedMemorySize, SP_TOT);
    cudaFuncSetAttribute((const void*)k_temporal, cudaFuncAttributeMaxDynamicSharedMemorySize, SMB_TOT);

    k_pre<<<dim3(EMB, 4), 256, smp>>>(W1, b1, pws, pbs);
    k_wtem<<<dim3(12, 16), 256, WT_SM>>>(teb, pwt);
    k_weff<<<dim3(8, 16), 256, WE_SM>>>(neb);
    k_spatial<<<dim3(N_, 2), 256, SP_TOT>>>(eb, neb);
    k_temporal<<<dim3(BT, 2), 256, SMB_TOT>>>(teb, pbt, W3, b3, out);
}

// round 14
// speedup vs baseline: 5.0821x; 1.0142x over previous
#include <cuda_runtime.h>
#include <cuda_bf16.h>
#include <cstdint>

#define B_    32
#define T_    24
#define N_    512
#define BT    768
#define DIN   64
#define HID   128
#define EMB   16
#define DOUT  2
#define NEG   0.01f

// Inter-kernel scratch
__device__ __nv_bfloat16 g_hi[(size_t)BT * N_ * HID];
__device__ __nv_bfloat16 g_lo[(size_t)BT * N_ * HID];
__device__ float g_P[(size_t)EMB * DIN * HID];
__device__ float g_pbe[(size_t)EMB * HID];
__device__ __nv_bfloat16 g_wt_hi[(size_t)BT * HID * HID];
__device__ __nv_bfloat16 g_wt_lo[(size_t)BT * HID * HID];
__device__ __nv_bfloat16 g_we_hi[(size_t)N_ * HID * DIN];
__device__ __nv_bfloat16 g_we_lo[(size_t)N_ * HID * DIN];

__device__ __forceinline__ float lrelu(float x) { return x >= 0.f ? x : NEG * x; }

__device__ __forceinline__ uint32_t smem_u32(const void* p) {
    uint32_t a;
    asm("{ .reg .u64 t; cvta.to.shared.u64 t, %1; cvt.u32.u64 %0, t; }" : "=r"(a) : "l"(p));
    return a;
}
__device__ __forceinline__ void ldsm_x4(uint32_t* r, uint32_t addr) {
    asm volatile("ldmatrix.sync.aligned.m8n8.x4.shared.b16 {%0,%1,%2,%3}, [%4];"
                 : "=r"(r[0]), "=r"(r[1]), "=r"(r[2]), "=r"(r[3]) : "r"(addr));
}
__device__ __forceinline__ void mma_bf16(float* d, const uint32_t* a, uint32_t b0, uint32_t b1) {
    asm volatile("mma.sync.aligned.m16n8k16.row.col.f32.bf16.bf16.f32 "
                 "{%0,%1,%2,%3}, {%4,%5,%6,%7}, {%8,%9}, {%0,%1,%2,%3};"
                 : "+f"(d[0]), "+f"(d[1]), "+f"(d[2]), "+f"(d[3])
                 : "r"(a[0]), "r"(a[1]), "r"(a[2]), "r"(a[3]), "r"(b0), "r"(b1));
}
__device__ __forceinline__ void cp16(uint32_t s, const void* g) {
    asm volatile("cp.async.cg.shared.global [%0], [%1], 16;" :: "r"(s), "l"(g));
}
#define CP_COMMIT() asm volatile("cp.async.commit_group;" ::: "memory")
#define CP_WAIT0()  asm volatile("cp.async.wait_group 0;" ::: "memory")
#define CP_WAIT1()  asm volatile("cp.async.wait_group 1;" ::: "memory")

__device__ __forceinline__ uint32_t pack_bf16_hi(float a, float b) {
    __nv_bfloat16 ha = __float2bfloat16(a), hb = __float2bfloat16(b);
    return (uint32_t)*(uint16_t*)&ha | ((uint32_t)*(uint16_t*)&hb << 16);
}
__device__ __forceinline__ void split_pack(float a, float b, uint32_t& hp, uint32_t& lp) {
    __nv_bfloat16 ha = __float2bfloat16(a), hb = __float2bfloat16(b);
    hp = (uint32_t)*(uint16_t*)&ha | ((uint32_t)*(uint16_t*)&hb << 16);
    lp = pack_bf16_hi(a - __bfloat162float(ha), b - __bfloat162float(hb));
}

#define MMA_FUSED_24(acc, ah0, ah1, al0, al1, bhA, bhB, blA, blB) do {     \
    mma_bf16(acc[0][0], ah0, bhA[0], bhA[1]);                              \
    mma_bf16(acc[0][1], ah0, bhA[2], bhA[3]);                              \
    mma_bf16(acc[0][2], ah0, bhB[0], bhB[1]);                              \
    mma_bf16(acc[0][3], ah0, bhB[2], bhB[3]);                              \
    mma_bf16(acc[1][0], ah1, bhA[0], bhA[1]);                              \
    mma_bf16(acc[1][1], ah1, bhA[2], bhA[3]);                              \
    mma_bf16(acc[1][2], ah1, bhB[0], bhB[1]);                              \
    mma_bf16(acc[1][3], ah1, bhB[2], bhB[3]);                              \
    mma_bf16(acc[0][0], al0, bhA[0], bhA[1]);                              \
    mma_bf16(acc[0][1], al0, bhA[2], bhA[3]);                              \
    mma_bf16(acc[0][2], al0, bhB[0], bhB[1]);                              \
    mma_bf16(acc[0][3], al0, bhB[2], bhB[3]);                              \
    mma_bf16(acc[1][0], al1, bhA[0], bhA[1]);                              \
    mma_bf16(acc[1][1], al1, bhA[2], bhA[3]);                              \
    mma_bf16(acc[1][2], al1, bhB[0], bhB[1]);                              \
    mma_bf16(acc[1][3], al1, bhB[2], bhB[3]);                              \
    mma_bf16(acc[0][0], ah0, blA[0], blA[1]);                              \
    mma_bf16(acc[0][1], ah0, blA[2], blA[3]);                              \
    mma_bf16(acc[0][2], ah0, blB[0], blB[1]);                              \
    mma_bf16(acc[0][3], ah0, blB[2], blB[3]);                              \
    mma_bf16(acc[1][0], ah1, blA[0], blA[1]);                              \
    mma_bf16(acc[1][1], ah1, blA[2], blA[3]);                              \
    mma_bf16(acc[1][2], ah1, blB[0], blB[1]);                              \
    mma_bf16(acc[1][3], ah1, blB[2], blB[3]);                              \
} while (0)

// ---------------------------------------------------------------------------
// k_pre
// ---------------------------------------------------------------------------
__global__ void __launch_bounds__(256)
k_pre(const float* __restrict__ W1, const float* __restrict__ b1,
      const float* __restrict__ pool_w, const float* __restrict__ pool_b)
{
    extern __shared__ float sp[];
    float* W1s = sp;
    float* Pl  = sp + 16 * HID;

    const int d  = blockIdx.x;
    const int r0 = blockIdx.y * 16;
    const int t  = threadIdx.x;
    const int rg = t >> 4, cg = t & 15;

    for (int e = t; e < 16 * HID; e += 256) W1s[e] = W1[r0 * HID + e];
    for (int e = t; e < HID * HID; e += 256) Pl[e] = pool_w[(size_t)d * HID * HID + e];
    __syncthreads();

    float acc[8];
#pragma unroll
    for (int j = 0; j < 8; j++) acc[j] = 0.f;

    const float* ar = W1s + rg * HID;
    const float* wc = Pl + cg * 8;
#pragma unroll 4
    for (int k = 0; k < HID; k++) {
        float a = ar[k];
        float4 w0 = *(const float4*)(wc + k * HID);
        float4 w1 = *(const float4*)(wc + k * HID + 4);
        acc[0] += a * w0.x; acc[1] += a * w0.y; acc[2] += a * w0.z; acc[3] += a * w0.w;
        acc[4] += a * w1.x; acc[5] += a * w1.y; acc[6] += a * w1.z; acc[7] += a * w1.w;
    }
#pragma unroll
    for (int j = 0; j < 8; j++)
        g_P[(size_t)d * DIN * HID + (r0 + rg) * HID + cg * 8 + j] = acc[j];

    if (blockIdx.y == 0 && t < HID) {
        float s = pool_b[d * HID + t];
#pragma unroll 8
        for (int k = 0; k < HID; k++) s += b1[k] * Pl[k * HID + t];
        g_pbe[d * HID + t] = s;
    }
}

// ---------------------------------------------------------------------------
// k_wtem
// ---------------------------------------------------------------------------
#define WT_PSLD 132
#define WT_SM   (16 * 8 * WT_PSLD * 4 + 256)

__global__ void __launch_bounds__(256)
k_wtem(const float* __restrict__ time_eb, const float* __restrict__ pool_w)
{
    extern __shared__ float sp[];
    float* Ps  = sp;
    float* tes = sp + 16 * 8 * WT_PSLD;

    const int btg0 = blockIdx.x * 64;
    const int o0   = blockIdx.y * 8;
    const int t    = threadIdx.x;

#pragma unroll
    for (int it = 0; it < 64; it++) {
        int idx = t + it * 256;
        int d = idx >> 10, rem = idx & 1023;
        int i = rem >> 3, orel = rem & 7;
        Ps[d * (8 * WT_PSLD) + orel * WT_PSLD + i] =
            pool_w[(size_t)d * HID * HID + i * HID + o0 + orel];
    }
    __syncthreads();

    const int orel = t >> 5;
    const int i0   = (t & 31) * 4;

#pragma unroll 1
    for (int gq = 0; gq < 16; gq++) {
        const int bt0 = btg0 + gq * 4;
        if (t < 64) tes[t] = time_eb[(bt0 + (t >> 4)) * EMB + (t & 15)];
        __syncthreads();

        float acc[4][4];
#pragma unroll
        for (int b = 0; b < 4; b++)
#pragma unroll
            for (int q = 0; q < 4; q++) acc[b][q] = 0.f;

#pragma unroll
        for (int d = 0; d < EMB; d++) {
            float4 p = *(const float4*)(Ps + d * (8 * WT_PSLD) + orel * WT_PSLD + i0);
#pragma unroll
            for (int b = 0; b < 4; b++) {
                float te = tes[b * EMB + d];
                acc[b][0] += te * p.x; acc[b][1] += te * p.y;
                acc[b][2] += te * p.z; acc[b][3] += te * p.w;
            }
        }
#pragma unroll
        for (int b = 0; b < 4; b++) {
            uint2 hp, lp;
            split_pack(acc[b][0], acc[b][1], hp.x, lp.x);
            split_pack(acc[b][2], acc[b][3], hp.y, lp.y);
            size_t off = (size_t)(bt0 + b) * HID * HID + (o0 + orel) * HID + i0;
            *(uint2*)(g_wt_hi + off) = hp;
            *(uint2*)(g_wt_lo + off) = lp;
        }
        __syncthreads();
    }
}

// ---------------------------------------------------------------------------
// k_weff
// ---------------------------------------------------------------------------
#define WE_PSLD 68
#define WE_SM   (16 * 8 * WE_PSLD * 4 + 256)

__global__ void __launch_bounds__(256)
k_weff(const float* __restrict__ node_eb)
{
    extern __shared__ float sp[];
    float* Ps  = sp;
    float* nes = sp + 16 * 8 * WE_PSLD;

    const int ng0 = blockIdx.x * 64;
    const int o0  = blockIdx.y * 8;
    const int t   = threadIdx.x;

#pragma unroll
    for (int it = 0; it < 32; it++) {
        int idx = t + it * 256;
        int d = idx >> 9, rem = idx & 511;
        int i = rem >> 3, orel = rem & 7;
        Ps[d * (8 * WE_PSLD) + orel * WE_PSLD + i] =
            g_P[(size_t)d * DIN * HID + i * HID + o0 + orel];
    }
    __syncthreads();

    const int orel = t >> 5;
    const int i0   = (t & 31) * 2;

#pragma unroll 1
    for (int gq = 0; gq < 16; gq++) {
        const int n0 = ng0 + gq * 4;
        if (t < 64) nes[t] = node_eb[(n0 + (t >> 4)) * EMB + (t & 15)];
        __syncthreads();

        float acc[4][2];
#pragma unroll
        for (int b = 0; b < 4; b++) { acc[b][0] = 0.f; acc[b][1] = 0.f; }

#pragma unroll
        for (int d = 0; d < EMB; d++) {
            float2 p = *(const float2*)(Ps + d * (8 * WE_PSLD) + orel * WE_PSLD + i0);
#pragma unroll
            for (int b = 0; b < 4; b++) {
                float ne = nes[b * EMB + d];
                acc[b][0] += ne * p.x; acc[b][1] += ne * p.y;
            }
        }
#pragma unroll
        for (int b = 0; b < 4; b++) {
            uint32_t hp, lp;
            split_pack(acc[b][0], acc[b][1], hp, lp);
            size_t off = (size_t)(n0 + b) * HID * DIN + (o0 + orel) * DIN + i0;
            *(uint32_t*)(g_we_hi + off) = hp;
            *(uint32_t*)(g_we_lo + off) = lp;
        }
        __syncthreads();
    }
}

// ---------------------------------------------------------------------------
// Kernel A (spatial): cp.async 2-stage raw-x ring + convert + fused MMA.
// smem: [bsp 512][BHI 18432][BLO 18432][AHI 9216][ALO 9216][XRAW 2x17408]
// = 90624 B -> 2 CTA/SM
// ---------------------------------------------------------------------------
#define SLD     144
#define SP_BSP  0
#define SP_BHI  512
#define SP_BLO  18944
#define SP_AHI  37376
#define SP_ALO  46592
#define SP_XRAW 55808
#define SP_TOT  90624

__device__ __forceinline__ void sp_load_x(uint32_t smb, const float* eb, int n,
                                          int c0, int stage, int t)
{
    uint32_t base = smb + SP_XRAW + (uint32_t)stage * 17408;
#pragma unroll
    for (int i = 0; i < 4; i++) {
        int chunk = t + i * 256;
        int r = chunk >> 4, q = chunk & 15;
        cp16(base + r * 272 + q * 16,
             eb + ((size_t)(c0 + r) * N_ + n) * DIN + q * 4);
    }
}

__global__ void __launch_bounds__(256, 2)
k_spatial(const float* __restrict__ eb, const float* __restrict__ node_eb)
{
    extern __shared__ char smch[];
    const uint32_t smb = smem_u32(smch);
    float* bsp = (float*)(smch + SP_BSP);

    const int n   = blockIdx.x;
    const int t   = threadIdx.x;
    const int wid = t >> 5;
    const int l   = t & 31;
    const int c_base = blockIdx.y * (BT / 2);

    // stage 0/1 x-tiles in flight immediately
    sp_load_x(smb, eb, n, c_base, 0, t);      CP_COMMIT();   // g0
    sp_load_x(smb, eb, n, c_base + 64, 1, t); CP_COMMIT();   // g1

    // B (materialized weights) + bias
#pragma unroll
    for (int i = 0; i < 4; i++) {
        int c = t + i * 256;
        int r = c >> 3, q = c & 7;
        size_t src = (size_t)n * HID * DIN + r * DIN + q * 8;
        *(uint4*)(smch + SP_BHI + r * SLD + q * 16) = *(const uint4*)(g_we_hi + src);
        *(uint4*)(smch + SP_BLO + r * SLD + q * 16) = *(const uint4*)(g_we_lo + src);
    }
    if (t < HID) {
        float s = 0.f;
#pragma unroll
        for (int d = 0; d < EMB; d++) s += node_eb[n * EMB + d] * g_pbe[d * HID + t];
        bsp[t] = s;
    }

    const int mw = wid & 1, nw = wid >> 1;
    const int m0w = mw * 32, n0w = nw * 32;
    const int g  = l >> 2, tq = l & 3;
    const uint32_t aoff = (uint32_t)(((l & 7) + ((l >> 3) & 1) * 8) * SLD + ((l >> 4) & 1) * 16);
    const uint32_t boff = (uint32_t)(((l & 7) + ((l >> 4) & 1) * 8) * SLD + ((l >> 3) & 1) * 16);
    const uint32_t AbHi = smb + SP_AHI + (uint32_t)m0w * SLD + aoff;
    const uint32_t AbLo = smb + SP_ALO + (uint32_t)m0w * SLD + aoff;
    const uint32_t BbHi = smb + SP_BHI + (uint32_t)n0w * SLD + boff;
    const uint32_t BbLo = smb + SP_BLO + (uint32_t)n0w * SLD + boff;

    CP_WAIT1();            // g0 (x tile 0) complete
    __syncthreads();

#pragma unroll 1
    for (int it = 0; it < 6; it++) {
        const int c0 = c_base + it * 64;

        // --- convert raw fp32 xraw[it&1] -> AHI/ALO (hi/lo bf16) ---
        const uint32_t xb = (uint32_t)(it & 1) * 17408;
#pragma unroll
        for (int i = 0; i < 4; i++) {
            int chunk = t + i * 256;
            int r = chunk >> 4, q = chunk & 15;
            float4 v = *(const float4*)(smch + SP_XRAW + xb + r * 272 + q * 16);
            uint2 uh, ul;
            split_pack(v.x, v.y, uh.x, ul.x);
            split_pack(v.z, v.w, uh.y, ul.y);
            *(uint2*)(smch + SP_AHI + r * SLD + q * 8) = uh;
            *(uint2*)(smch + SP_ALO + r * SLD + q * 8) = ul;
        }
        __syncthreads();

        // prefetch x tile it+2 into the stage just freed
        if (it + 2 < 6) { sp_load_x(smb, eb, n, c_base + (it + 2) * 64, it & 1, t); CP_COMMIT(); }

        float acc[2][4][4];
#pragma unroll
        for (int mi = 0; mi < 2; mi++)
#pragma unroll
            for (int nj = 0; nj < 4; nj++)
#pragma unroll
                for (int q = 0; q < 4; q++) acc[mi][nj][q] = 0.f;

#pragma unroll
        for (int kc = 0; kc < 4; kc++) {
            uint32_t ah0[4], ah1[4], al0[4], al1[4], bhA[4], bhB[4], blA[4], blB[4];
            ldsm_x4(ah0, AbHi + kc * 32);
            ldsm_x4(ah1, AbHi + 16 * SLD + kc * 32);
            ldsm_x4(al0, AbLo + kc * 32);
            ldsm_x4(al1, AbLo + 16 * SLD + kc * 32);
            ldsm_x4(bhA, BbHi + kc * 32);
            ldsm_x4(bhB, BbHi + 16 * SLD + kc * 32);
            ldsm_x4(blA, BbLo + kc * 32);
            ldsm_x4(blB, BbLo + 16 * SLD + kc * 32);
            MMA_FUSED_24(acc, ah0, ah1, al0, al1, bhA, bhB, blA, blB);
        }

#pragma unroll
        for (int mi = 0; mi < 2; mi++) {
#pragma unroll
            for (int rh = 0; rh < 2; rh++) {
                const int row = m0w + 16 * mi + 8 * rh + g;
                const size_t base = ((size_t)(c0 + row) * N_ + n) * HID;
#pragma unroll
                for (int nj = 0; nj < 4; nj++) {
                    const int col = n0w + 8 * nj + 2 * tq;
                    float h0 = lrelu(acc[mi][nj][rh * 2 + 0] + bsp[col]);
                    float h1 = lrelu(acc[mi][nj][rh * 2 + 1] + bsp[col + 1]);
                    uint32_t hp, lp;
                    split_pack(h0, h1, hp, lp);
                    *(uint32_t*)(g_hi + base + col) = hp;
                    *(uint32_t*)(g_lo + base + col) = lp;
                }
            }
        }

        if (it + 2 < 6) CP_WAIT1(); else CP_WAIT0();
        __syncthreads();
    }
}

// ---------------------------------------------------------------------------
// Kernel B (temporal): 512 threads, one CTA per bt, M-tiles of 128 rows,
// cp.async 2-stage A ring. smem:
//   [btm 512][W3s 1024][pout 1024][BHI 34816][BLO 34816][A 2x69632] = 211456
// ---------------------------------------------------------------------------
#define TLD    272
#define T_BTM  0
#define T_W3   512
#define T_POUT 1536
#define T_BHI  2560
#define T_BLO  37376
#define T_AST  72192
#define T_TOT  211456

__device__ __forceinline__ void tm_load_a(uint32_t smb, int bt, int r0, int stage, int t)
{
    uint32_t base = smb + T_AST + (uint32_t)stage * 69632;
#pragma unroll
    for (int i = 0; i < 4; i++) {
        int idx = t + i * 512;
        int r = idx >> 4, q = idx & 15;
        size_t src = ((size_t)bt * N_ + r0 + r) * HID + q * 8;
        cp16(base + r * TLD + q * 16, g_hi + src);
        cp16(base + 34816 + r * TLD + q * 16, g_lo + src);
    }
}

__global__ void __launch_bounds__(512, 1)
k_temporal(const float* __restrict__ time_eb,
           const float* __restrict__ pool_b,
           const float* __restrict__ W3,
           const float* __restrict__ b3,
           float* __restrict__ out)
{
    extern __shared__ char smch[];
    const uint32_t smb = smem_u32(smch);
    float* btm  = (float*)(smch + T_BTM);
    float* W3s  = (float*)(smch + T_W3);
    float* pout = (float*)(smch + T_POUT);

    const int bt  = blockIdx.x;
    const int t   = threadIdx.x;
    const int wid = t >> 5;
    const int l   = t & 31;

    // group0: B (hi+lo) + A tile0
#pragma unroll
    for (int i = 0; i < 4; i++) {
        int idx = t + i * 512;
        int r = idx >> 4, q = idx & 15;
        size_t src = (size_t)bt * HID * HID + r * HID + q * 8;
        cp16(smb + T_BHI + r * TLD + q * 16, g_wt_hi + src);
        cp16(smb + T_BLO + r * TLD + q * 16, g_wt_lo + src);
    }
    tm_load_a(smb, bt, 0, 0, t);
    CP_COMMIT();                         // g0
    tm_load_a(smb, bt, 128, 1, t);
    CP_COMMIT();                         // g1

    if (t < HID) {
        float s = 0.f;
#pragma unroll
        for (int d = 0; d < EMB; d++) s += time_eb[bt * EMB + d] * pool_b[d * HID + t];
        btm[t] = s;
    }
    if (t < HID * DOUT) W3s[t] = W3[t];
    const float b30 = __ldg(b3), b31 = __ldg(b3 + 1);
    if (t < 256) pout[t] = (t & 1) ? b31 : b30;

    const int mw = wid & 3, nw = wid >> 2;
    const int m0w = mw * 32, n0w = nw * 32;
    const int g  = l >> 2, tq = l & 3;
    const uint32_t aoff = (uint32_t)(((l & 7) + ((l >> 3) & 1) * 8) * TLD + ((l >> 4) & 1) * 16);
    const uint32_t boff = (uint32_t)(((l & 7) + ((l >> 4) & 1) * 8) * TLD + ((l >> 3) & 1) * 16);
    const uint32_t BbHi = smb + T_BHI + (uint32_t)n0w * TLD + boff;
    const uint32_t BbLo = BbHi + 34816;

    CP_WAIT1();            // g0 complete (B + A0)
    __syncthreads();

#pragma unroll 1
    for (int tile = 0; tile < 4; tile++) {
        const int r0 = tile * 128;
        const uint32_t AbHi = smb + T_AST + (uint32_t)(tile & 1) * 69632
                            + (uint32_t)m0w * TLD + aoff;
        const uint32_t AbLo = AbHi + 34816;

        float acc[2][4][4];
#pragma unroll
        for (int mi = 0; mi < 2; mi++)
#pragma unroll
            for (int nj = 0; nj < 4; nj++)
#pragma unroll
                for (int q = 0; q < 4; q++) acc[mi][nj][q] = 0.f;

#pragma unroll 2
        for (int kc = 0; kc < 8; kc++) {
            uint32_t ah0[4], ah1[4], al0[4], al1[4], bhA[4], bhB[4], blA[4], blB[4];
            ldsm_x4(ah0, AbHi + kc * 32);
            ldsm_x4(ah1, AbHi + 16 * TLD + kc * 32);
            ldsm_x4(al0, AbLo + kc * 32);
            ldsm_x4(al1, AbLo + 16 * TLD + kc * 32);
            ldsm_x4(bhA, BbHi + kc * 32);
            ldsm_x4(bhB, BbHi + 16 * TLD + kc * 32);
            ldsm_x4(blA, BbLo + kc * 32);
            ldsm_x4(blB, BbLo + 16 * TLD + kc * 32);
            MMA_FUSED_24(acc, ah0, ah1, al0, al1, bhA, bhB, blA, blB);
        }

        // epilogue: h = leaky(D + btm); p = h@W3; reduce into pout
#pragma unroll
        for (int mi = 0; mi < 2; mi++) {
#pragma unroll
            for (int rh = 0; rh < 2; rh++) {
                int rowl = m0w + 16 * mi + 8 * rh + g;
                float p0 = 0.f, p1 = 0.f;
#pragma unroll
                for (int nj = 0; nj < 4; nj++) {
                    int col = n0w + 8 * nj + 2 * tq;
                    float h0 = lrelu(acc[mi][nj][rh * 2 + 0] + btm[col]);
                    float h1 = lrelu(acc[mi][nj][rh * 2 + 1] + btm[col + 1]);
                    p0 += h0 * W3s[col * 2 + 0] + h1 * W3s[(col + 1) * 2 + 0];
                    p1 += h0 * W3s[col * 2 + 1] + h1 * W3s[(col + 1) * 2 + 1];
                }
                p0 += __shfl_xor_sync(0xffffffffu, p0, 1);
                p1 += __shfl_xor_sync(0xffffffffu, p1, 1);
                p0 += __shfl_xor_sync(0xffffffffu, p0, 2);
                p1 += __shfl_xor_sync(0xffffffffu, p1, 2);
                if (tq == 0) {
                    atomicAdd(&pout[rowl * 2 + 0], p0);
                    atomicAdd(&pout[rowl * 2 + 1], p1);
                }
            }
        }
        __syncthreads();   // pout complete; stage[tile&1] fully consumed

        if (t < 256) out[((size_t)bt * N_ + r0) * DOUT + t] = pout[t];

        if (tile < 3) {
            if (t < 256) pout[t] = (t & 1) ? b31 : b30;
            if (tile < 2) {
                tm_load_a(smb, bt, (tile + 2) * 128, tile & 1, t);
                CP_COMMIT();
                CP_WAIT1();     // next tile's stage ready
            } else {
                CP_WAIT0();
            }
            __syncthreads();
        }
    }
}

// ---------------------------------------------------------------------------
extern "C" void kernel_launch(void* const* d_in, const int* in_sizes, int n_in,
                              void* d_out, int out_size)
{
    const float* eb   = (const float*)d_in[0];
    const float* teb  = (const float*)d_in[1];
    const float* neb  = (const float*)d_in[2];
    const float* W1   = (const float*)d_in[3];
    const float* b1   = (const float*)d_in[4];
    const float* W3   = (const float*)d_in[5];
    const float* b3   = (const float*)d_in[6];
    const float* pws  = (const float*)d_in[7];
    const float* pbs  = (const float*)d_in[8];
    const float* pwt  = (const float*)d_in[9];
    const float* pbt  = (const float*)d_in[10];
    float* out = (float*)d_out;

    const int smp = (16 * HID + HID * HID) * sizeof(float);

    cudaFuncSetAttribute((const void*)k_pre,      cudaFuncAttributeMaxDynamicSharedMemorySize, smp);
    cudaFuncSetAttribute((const void*)k_wtem,     cudaFuncAttributeMaxDynamicSharedMemorySize, WT_SM);
    cudaFuncSetAttribute((const void*)k_weff,     cudaFuncAttributeMaxDynamicSharedMemorySize, WE_SM);
    cudaFuncSetAttribute((const void*)k_spatial,  cudaFuncAttributeMaxDynamicSharedMemorySize, SP_TOT);
    cudaFuncSetAttribute((const void*)k_temporal, cudaFuncAttributeMaxDynamicSharedMemorySize, T_TOT);

    k_pre<<<dim3(EMB, 4), 256, smp>>>(W1, b1, pws, pbs);
    k_wtem<<<dim3(12, 16), 256, WT_SM>>>(teb, pwt);
    k_weff<<<dim3(8, 16), 256, WE_SM>>>(neb);
    k_spatial<<<dim3(N_, 2), 256, SP_TOT>>>(eb, neb);
    k_temporal<<<BT, 512, T_TOT>>>(teb, pbt, W3, b3, out);
}